// round 10
// baseline (speedup 1.0000x reference)
#include <cuda_runtime.h>
#include <cuda_bf16.h>
#include <math.h>
#include <stdint.h>
#include <stddef.h>

// ============================================================================
// biSoftmax on GB300 via HMMA (mma.sync bf16) split-precision GEMMs.
// R10: (1) one __syncthreads per TWO 32-k steps (4-slab ring, fetch-2 after
//      sync -- race-free since those slabs were last read before the previous
//      sync); (2) score fusion: score1-score2 = [A1|A2] @ [W1|-W2]^T as a
//      single K=4096 GEMM whose epilogue squares into bf16 pairs (circle),
//      deleting diffsq + the fp32 score round-trip.
// All GEMMs are NT: C[m,n] = alpha * sum_k A[m,k] * B[n,k]
// fp32 operands stored as bf16 (hi,lo); accumulate Ahi*Bhi + Ahi*Blo + Alo*Bhi.
// ============================================================================

#define SEQ 2048
#define NH 8
#define MROWS (NH * SEQ)                 // 16384
#define SSZ ((size_t)SEQ * SEQ)          // 2^22
#define NTOT ((size_t)MROWS * SEQ)       // 2^25

typedef __nv_bfloat16 bf16;

// ---------------- scratch (device globals, allocation-free) ----------------
__device__ bf16 g_xh[NTOT],       g_xl[NTOT];
__device__ bf16 g_Wvh[SSZ],       g_Wvl[SSZ];        // Wv
__device__ bf16 g_Wch[2 * SSZ],   g_Wcl[2 * SSZ];    // Wcat = [W1 | -W2], ld 4096
__device__ bf16 g_WTqh[2 * SSZ],  g_WTql[2 * SSZ];   // Wq1^T, Wq2^T
__device__ bf16 g_WTkh[2 * SSZ],  g_WTkl[2 * SSZ];   // Wk1^T, Wk2^T
__device__ bf16 g_Nh[2 * SSZ],    g_Nl[2 * SSZ];     // N_i = Wk_i^T Wq_i
__device__ bf16 g_Th[2 * NTOT],   g_Tl[2 * NTOT];    // T_i = X N_i^T
__device__ bf16 g_Vth[NTOT],      g_Vtl[NTOT];       // [h][e][t]
__device__ bf16 g_Ah[2 * NTOT],   g_Al[2 * NTOT];    // Acat: [h*S+s][4096]
__device__ bf16 g_Ch[NTOT],       g_Cl[NTOT];        // circle
__device__ float g_S[2 * NTOT];                      // logits (fp32)

// ---------------- PTX helpers ----------------
__device__ __forceinline__ uint32_t smem_u32(const void* p) {
    uint32_t a;
    asm("{ .reg .u64 t; cvta.to.shared.u64 t, %1; cvt.u32.u64 %0, t; }" : "=r"(a) : "l"(p));
    return a;
}

#define CP16(dst, src) \
    asm volatile("cp.async.cg.shared.global [%0], [%1], 16;" :: "r"(dst), "l"(src) : "memory")
#define CP_COMMIT() asm volatile("cp.async.commit_group;" ::: "memory")
#define CP_WAIT0()  asm volatile("cp.async.wait_group 0;" ::: "memory")

#define LDSM4(r0, r1, r2, r3, a) \
    asm volatile("ldmatrix.sync.aligned.m8n8.x4.shared.b16 {%0,%1,%2,%3}, [%4];" \
        : "=r"(r0), "=r"(r1), "=r"(r2), "=r"(r3) : "r"(a))

#define MMA_BF16(d, a, b) \
    asm volatile("mma.sync.aligned.m16n8k16.row.col.f32.bf16.bf16.f32 " \
        "{%0,%1,%2,%3}, {%4,%5,%6,%7}, {%8,%9}, {%0,%1,%2,%3};" \
        : "+f"((d)[0]), "+f"((d)[1]), "+f"((d)[2]), "+f"((d)[3]) \
        : "r"((a)[0]), "r"((a)[1]), "r"((a)[2]), "r"((a)[3]), "r"((b)[0]), "r"((b)[1]))

// ---------------- HMMA split-precision GEMM ----------------
// CTA tile 256x128, 512 threads (16 warps of 64x32), 1 CTA/SM.
// 4 slabs of BK=32; ONE __syncthreads per TWO slabs.
// smem row = 32 bf16 = 64B packed; chunk c of row r at r*64+((c^((r>>1)&3))<<4).
// Slab: Ahi[0,16K) Alo[16K,32K) Bhi[32K,40K) Blo[40K,48K)  (49152 B)
static constexpr int STAGE_B = 49152;
static constexpr int SMEM_HG = 4 * STAGE_B;   // 196608

// z decomposition: zi = z>>3, zr = z&7; row offsets = zi*Hi + zr*Lo
// EPI: 0 = fp32 * alpha, 1 = bf16 (hi,lo) pair, 2 = square -> bf16 pair
template <int EPI>
__global__ __launch_bounds__(512, 1)
void hgemm3(const bf16* __restrict__ Ah, const bf16* __restrict__ Al,
            const bf16* __restrict__ Bh, const bf16* __restrict__ Bl,
            float* __restrict__ Cf, bf16* __restrict__ Ch, bf16* __restrict__ Cl,
            int K, int ldc, size_t sC,
            int azHi, int azLo, int bzHi, int bzLo, float alpha)
{
    extern __shared__ char smem[];
    const uint32_t sbase = smem_u32(smem);
    const int tid  = threadIdx.x;
    const int lane = tid & 31;
    const int wid  = tid >> 5;          // 0..15
    const int wm   = wid >> 2;          // 0..3 -> 64-row slab
    const int wn   = wid & 3;           // 0..3 -> 32-col slab
    const int row0 = blockIdx.y * 256;
    const int col0 = blockIdx.x * 128;
    const int z    = blockIdx.z;
    const int zi   = z >> 3, zr = z & 7;
    const int aoff = zi * azHi + zr * azLo;
    const int boff = zi * bzHi + zr * bzLo;

    // ---- loader lanes ----
    const int lrA  = tid >> 1;          // 0..255
    const int lcb  = (tid & 1) * 2;     // chunk 0 or 2
    const size_t arow = (size_t)(row0 + aoff + lrA);
    const bf16* pAh = Ah + arow * K + lcb * 8;
    const bf16* pAl = Al + arow * K + lcb * 8;
    const uint32_t lswA = (uint32_t)((lrA >> 1) & 3);
    const uint32_t stA1 = lrA * 64 + (((uint32_t)lcb ^ lswA) << 4);
    const uint32_t stA2 = lrA * 64 + ((((uint32_t)lcb + 1u) ^ lswA) << 4);
    const int lrB = tid >> 2;           // 0..127
    const int lcB = tid & 3;            // 0..3
    const size_t brow = (size_t)(col0 + boff + lrB);
    const bf16* pBh = Bh + brow * K + lcB * 8;
    const bf16* pBl = Bl + brow * K + lcB * 8;
    const uint32_t lswB = (uint32_t)((lrB >> 1) & 3);
    const uint32_t stB  = lrB * 64 + (((uint32_t)lcB ^ lswB) << 4);

    auto prefetch = [&](int go, int stage) {
        const uint32_t sb = sbase + (uint32_t)stage * STAGE_B;
        CP16(sb +          stA1, pAh + go); CP16(sb +          stA2, pAh + go + 8);
        CP16(sb + 16384u + stA1, pAl + go); CP16(sb + 16384u + stA2, pAl + go + 8);
        CP16(sb + 32768u + stB,  pBh + go);
        CP16(sb + 40960u + stB,  pBl + go);
    };

    // ---- fragment addressing ----
    const int lr16  = lane & 15;
    const uint32_t khalf = (uint32_t)(lane >> 4);
    const uint32_t fsw   = (uint32_t)((lr16 >> 1) & 3);
    uint32_t a_base[4], b_base[2];
    #pragma unroll
    for (int mi = 0; mi < 4; mi++) a_base[mi] = (uint32_t)(wm * 64 + mi * 16 + lr16) * 64u;
    #pragma unroll
    for (int g = 0; g < 2; g++)    b_base[g]  = (uint32_t)(wn * 32 + g * 16 + lr16) * 64u;

    float acc[4][4][4];
    #pragma unroll
    for (int mi = 0; mi < 4; mi++)
        #pragma unroll
        for (int nj = 0; nj < 4; nj++)
            #pragma unroll
            for (int q = 0; q < 4; q++) acc[mi][nj][q] = 0.0f;

    auto compute_slab = [&](uint32_t stg) {
        #pragma unroll
        for (int ks = 0; ks < 2; ks++) {
            const uint32_t coff = ((((uint32_t)(ks * 2) + khalf) ^ fsw) << 4);
            uint32_t Bhi[4][2], Blo[4][2];
            #pragma unroll
            for (int g = 0; g < 2; g++) {
                uint32_t q0, q1, q2, q3;
                LDSM4(q0, q1, q2, q3, stg + 32768u + b_base[g] + coff);
                Bhi[2 * g][0] = q0;     Bhi[2 * g][1] = q2;
                Bhi[2 * g + 1][0] = q1; Bhi[2 * g + 1][1] = q3;
                LDSM4(q0, q1, q2, q3, stg + 40960u + b_base[g] + coff);
                Blo[2 * g][0] = q0;     Blo[2 * g][1] = q2;
                Blo[2 * g + 1][0] = q1; Blo[2 * g + 1][1] = q3;
            }
            #pragma unroll
            for (int mi = 0; mi < 4; mi++) {
                uint32_t Ahi[4], Alo[4];
                LDSM4(Ahi[0], Ahi[1], Ahi[2], Ahi[3], stg + a_base[mi] + coff);
                LDSM4(Alo[0], Alo[1], Alo[2], Alo[3], stg + 16384u + a_base[mi] + coff);
                #pragma unroll
                for (int nj = 0; nj < 4; nj++) MMA_BF16(acc[mi][nj], Ahi, Bhi[nj]);
                #pragma unroll
                for (int nj = 0; nj < 4; nj++) MMA_BF16(acc[mi][nj], Ahi, Blo[nj]);
                #pragma unroll
                for (int nj = 0; nj < 4; nj++) MMA_BF16(acc[mi][nj], Alo, Bhi[nj]);
            }
        }
    };

    const int nk = K >> 5;   // always even here (K multiple of 2048)

    prefetch(0, 0); prefetch(32, 1); CP_COMMIT();

    int gof = 64;
    for (int kt = 0; kt < nk; kt += 2) {
        CP_WAIT0();
        __syncthreads();
        // stages (kt+2)&3, (kt+3)&3 were last READ before the previous sync ->
        // free to refill now; the fetch overlaps both slab computes below.
        if (kt + 2 < nk) {
            prefetch(gof,      (kt + 2) & 3);
            prefetch(gof + 32, (kt + 3) & 3);
            gof += 64;
        }
        CP_COMMIT();

        compute_slab(sbase + (uint32_t)(kt & 3) * STAGE_B);
        compute_slab(sbase + (uint32_t)((kt + 1) & 3) * STAGE_B);
    }

    // ---- epilogue ----
    const size_t cb = (size_t)z * sC;
    #pragma unroll
    for (int mi = 0; mi < 4; mi++) {
        #pragma unroll
        for (int nj = 0; nj < 4; nj++) {
            const int rg = row0 + wm * 64 + mi * 16 + (lane >> 2);
            const int cg = col0 + wn * 32 + nj * 8 + (lane & 3) * 2;
            float d0 = acc[mi][nj][0] * alpha, d1 = acc[mi][nj][1] * alpha;
            float d2 = acc[mi][nj][2] * alpha, d3 = acc[mi][nj][3] * alpha;
            if (EPI == 2) { d0 *= d0; d1 *= d1; d2 *= d2; d3 *= d3; }
            const size_t i0 = cb + (size_t)rg * ldc + cg;
            const size_t i1 = cb + (size_t)(rg + 8) * ldc + cg;
            if (EPI == 0) {
                *(float2*)(Cf + i0) = make_float2(d0, d1);
                *(float2*)(Cf + i1) = make_float2(d2, d3);
            } else {
                __nv_bfloat162 h, l;
                h.x = __float2bfloat16(d0);
                h.y = __float2bfloat16(d1);
                l.x = __float2bfloat16(d0 - __bfloat162float(h.x));
                l.y = __float2bfloat16(d1 - __bfloat162float(h.y));
                *(__nv_bfloat162*)(Ch + i0) = h;
                *(__nv_bfloat162*)(Cl + i0) = l;
                h.x = __float2bfloat16(d2);
                h.y = __float2bfloat16(d3);
                l.x = __float2bfloat16(d2 - __bfloat162float(h.x));
                l.y = __float2bfloat16(d3 - __bfloat162float(h.y));
                *(__nv_bfloat162*)(Ch + i1) = h;
                *(__nv_bfloat162*)(Cl + i1) = l;
            }
        }
    }
}

// ---------------- conversions ----------------
struct WPtrs3 { const float* p[3]; };   // Wv, W1, W2
struct WPtrs4 { const float* p[4]; };   // Wq1, Wk1, Wq2, Wk2

// y==0: x -> pair. y==1: Wv -> pair; Wcat=[W1|-W2] (ld 4096) -> pair.
__global__ __launch_bounds__(256)
void convert_all(const float* __restrict__ x, WPtrs3 w,
                 bf16* __restrict__ xh, bf16* __restrict__ xl,
                 bf16* __restrict__ Wvh, bf16* __restrict__ Wvl,
                 bf16* __restrict__ Wch, bf16* __restrict__ Wcl)
{
    const size_t stride = (size_t)gridDim.x * blockDim.x;
    size_t i = (size_t)blockIdx.x * blockDim.x + threadIdx.x;
    if (blockIdx.y == 0) {
        for (; i < NTOT; i += stride) {
            float f = x[i];
            bf16 h = __float2bfloat16(f);
            xh[i] = h;
            xl[i] = __float2bfloat16(f - __bfloat162float(h));
        }
    } else {
        const size_t n = 3 * SSZ;
        for (; i < n; i += stride) {
            if (i < SSZ) {
                float f = w.p[0][i];
                bf16 h = __float2bfloat16(f);
                Wvh[i] = h;
                Wvl[i] = __float2bfloat16(f - __bfloat162float(h));
            } else {
                const size_t j = i - SSZ;
                const size_t u = j >> 12;          // row (4096 cols)
                const int k = (int)(j & 4095);
                float f = (k < SEQ) ? w.p[1][u * SEQ + k]
                                    : -w.p[2][u * SEQ + (k - SEQ)];
                bf16 h = __float2bfloat16(f);
                Wch[j] = h;
                Wcl[j] = __float2bfloat16(f - __bfloat162float(h));
            }
        }
    }
}

// Transpose Wq1,Wk1,Wq2,Wk2 (fp32 [SEQ,SEQ]) -> bf16 (hi,lo) pairs.
__global__ __launch_bounds__(256)
void transpose_pairs(WPtrs4 w,
                     bf16* __restrict__ WTqh, bf16* __restrict__ WTql,
                     bf16* __restrict__ WTkh, bf16* __restrict__ WTkl)
{
    __shared__ float t[32][33];
    const int z = blockIdx.z;
    const float* src = w.p[z];
    bf16* dh = (z & 1) ? WTkh : WTqh;
    bf16* dl = (z & 1) ? WTkl : WTql;
    const size_t base = (z >> 1) ? SSZ : 0;

    const int tx = threadIdx.x, ty = threadIdx.y;   // 32 x 8
    const int x = blockIdx.x * 32 + tx;
    const int y = blockIdx.y * 32 + ty;
    #pragma unroll
    for (int r = 0; r < 4; r++)
        t[ty + r * 8][tx] = src[(size_t)(y + r * 8) * SEQ + x];
    __syncthreads();
    const int x2 = blockIdx.y * 32 + tx;
    const int y2 = blockIdx.x * 32 + ty;
    #pragma unroll
    for (int r = 0; r < 4; r++) {
        float f = t[tx][ty + r * 8];
        bf16 h = __float2bfloat16(f);
        const size_t idx = base + (size_t)(y2 + r * 8) * SEQ + x2;
        dh[idx] = h;
        dl[idx] = __float2bfloat16(f - __bfloat162float(h));
    }
}

// softmax of S row r (r in [0, 2*MROWS)); writes into Acat[h*S+s][i*2048 + :]
__global__ __launch_bounds__(256)
void softmax_cat(const float* __restrict__ S, bf16* __restrict__ Ph,
                 bf16* __restrict__ Pl)
{
    const int tid = threadIdx.x;
    const int r = blockIdx.x;
    const int branch = r >> 14;           // 0 or 1 (MROWS = 2^14)
    const int hs = r & (MROWS - 1);
    const float* p = S + (size_t)r * SEQ;
    const size_t dst = (size_t)hs * 4096 + (size_t)branch * SEQ;
    bf16* oh = Ph + dst;
    bf16* ol = Pl + dst;
    __shared__ float buf[SEQ];
    __shared__ float red[256];

    float m = -INFINITY;
    for (int i = tid; i < SEQ; i += 256) { float v = p[i]; buf[i] = v; m = fmaxf(m, v); }
    red[tid] = m; __syncthreads();
    for (int s = 128; s > 0; s >>= 1) { if (tid < s) red[tid] = fmaxf(red[tid], red[tid + s]); __syncthreads(); }
    m = red[0]; __syncthreads();

    float sum = 0.0f;
    for (int i = tid; i < SEQ; i += 256) { float e = __expf(buf[i] - m); buf[i] = e; sum += e; }
    red[tid] = sum; __syncthreads();
    for (int s = 128; s > 0; s >>= 1) { if (tid < s) red[tid] += red[tid + s]; __syncthreads(); }
    const float inv = 1.0f / red[0]; __syncthreads();

    for (int i = tid; i < SEQ; i += 256) {
        float f = buf[i] * inv;
        bf16 h = __float2bfloat16(f);
        oh[i] = h;
        ol[i] = __float2bfloat16(f - __bfloat162float(h));
    }
}

// ---------------- host side ----------------
template <typename T>
static T* sym_addr(T* symbol) {
    void* p = nullptr;
    cudaGetSymbolAddress(&p, (const void*)symbol);
    return (T*)p;
}

// Mrows multiple of 256; K multiple of 2048; lda = ldb = K.
static void run_hgemm(const bf16* Ah, const bf16* Al, int azHi, int azLo,
                      const bf16* Bh, const bf16* Bl, int bzHi, int bzLo,
                      int Mrows, int Ncols, int K, int ldc, int batch, int epi,
                      float* Cf, bf16* Ch, bf16* Cl, size_t sC, float alpha)
{
    dim3 grid(Ncols / 128, Mrows / 256, batch);
    if (epi == 0)
        hgemm3<0><<<grid, 512, SMEM_HG>>>(Ah, Al, Bh, Bl, Cf, Ch, Cl,
                                          K, ldc, sC, azHi, azLo, bzHi, bzLo, alpha);
    else if (epi == 1)
        hgemm3<1><<<grid, 512, SMEM_HG>>>(Ah, Al, Bh, Bl, Cf, Ch, Cl,
                                          K, ldc, sC, azHi, azLo, bzHi, bzLo, alpha);
    else
        hgemm3<2><<<grid, 512, SMEM_HG>>>(Ah, Al, Bh, Bl, Cf, Ch, Cl,
                                          K, ldc, sC, azHi, azLo, bzHi, bzLo, alpha);
}

extern "C" void kernel_launch(void* const* d_in, const int* in_sizes, int n_in,
                              void* d_out, int out_size)
{
    (void)in_sizes; (void)n_in; (void)out_size;
    const float* x = (const float*)d_in[0];
    WPtrs4 wqk;
    wqk.p[0] = (const float*)d_in[1];   // Wq1
    wqk.p[1] = (const float*)d_in[2];   // Wk1
    wqk.p[2] = (const float*)d_in[3];   // Wq2
    wqk.p[3] = (const float*)d_in[4];   // Wk2
    WPtrs3 wv;
    wv.p[0] = (const float*)d_in[5];    // Wv
    wv.p[1] = (const float*)d_in[6];    // W1
    wv.p[2] = (const float*)d_in[7];    // W2
    float* out = (float*)d_out;

    cudaFuncSetAttribute((const void*)hgemm3<0>,
                         cudaFuncAttributeMaxDynamicSharedMemorySize, SMEM_HG);
    cudaFuncSetAttribute((const void*)hgemm3<1>,
                         cudaFuncAttributeMaxDynamicSharedMemorySize, SMEM_HG);
    cudaFuncSetAttribute((const void*)hgemm3<2>,
                         cudaFuncAttributeMaxDynamicSharedMemorySize, SMEM_HG);

    bf16 *xh = sym_addr(g_xh),   *xl = sym_addr(g_xl);
    bf16 *Wvh = sym_addr(g_Wvh), *Wvl = sym_addr(g_Wvl);
    bf16 *Wch = sym_addr(g_Wch), *Wcl = sym_addr(g_Wcl);
    bf16 *WTqh = sym_addr(g_WTqh), *WTql = sym_addr(g_WTql);
    bf16 *WTkh = sym_addr(g_WTkh), *WTkl = sym_addr(g_WTkl);
    bf16 *Nhh = sym_addr(g_Nh),  *Nll = sym_addr(g_Nl);
    bf16 *Thh = sym_addr(g_Th),  *Tll = sym_addr(g_Tl);
    bf16 *Vth = sym_addr(g_Vth), *Vtl = sym_addr(g_Vtl);
    bf16 *Ahh = sym_addr(g_Ah),  *All = sym_addr(g_Al);
    bf16 *Chh = sym_addr(g_Ch),  *Cll = sym_addr(g_Cl);
    float *S = sym_addr(g_S);

    const float scale = 1.0f / sqrtf((float)SEQ);

    // [0] conversions: x, Wv, Wcat=[W1|-W2]
    convert_all<<<dim3(1024, 2), 256>>>(x, wv, xh, xl, Wvh, Wvl, Wch, Wcl);

    // [1] transposes: Wq1,Wk1,Wq2,Wk2 -> WTq/WTk bf16 pairs
    transpose_pairs<<<dim3(SEQ / 32, SEQ / 32, 4), dim3(32, 8)>>>(
        wqk, WTqh, WTql, WTkh, WTkl);

    // [2] N_i = WTk_i @ WTq_i^T   (z = i, 2 batches)
    run_hgemm(WTkh, WTkl, 0, SEQ, WTqh, WTql, 0, SEQ,
              SEQ, SEQ, SEQ, SEQ, 2, 1, nullptr, Nhh, Nll, SSZ, 1.0f);

    // [3] T_i = X @ N_i^T   (z = i, full M = 16384)
    run_hgemm(xh, xl, 0, 0, Nhh, Nll, 0, SEQ,
              MROWS, SEQ, SEQ, SEQ, 2, 1, nullptr, Thh, Tll, NTOT, 1.0f);

    // [4] Vt[h] = Wv @ X[h]^T   (z = head)
    run_hgemm(Wvh, Wvl, 0, 0, xh, xl, 0, SEQ,
              SEQ, SEQ, SEQ, SEQ, NH, 1, nullptr, Vth, Vtl, SSZ, 1.0f);

    // [5] logits: S[i][h] = scale * T_i[h] @ X[h]^T   (z = i*8+h, 16 batches)
    run_hgemm(Thh, Tll, MROWS, SEQ, xh, xl, 0, SEQ,
              SEQ, SEQ, SEQ, SEQ, 2 * NH, 0, S, nullptr, nullptr, SSZ, scale);

    // [6] softmax rows -> Acat bf16 pairs ([h*S+s][branch*2048 + :], ld 4096)
    softmax_cat<<<2 * MROWS, 256>>>(S, Ahh, All);

    // [7] circle[h] = (Acat[h] @ Wcat^T)^2  -- K=4096, squared epilogue
    run_hgemm(Ahh, All, 0, SEQ, Wch, Wcl, 0, 0,
              SEQ, SEQ, 2 * SEQ, SEQ, NH, 2, nullptr, Chh, Cll, SSZ, 1.0f);

    // [8] out[h] = circle[h] @ Vt[h]^T -> fp32
    run_hgemm(Chh, Cll, 0, SEQ, Vth, Vtl, 0, SEQ,
              SEQ, SEQ, SEQ, SEQ, NH, 0, out, nullptr, nullptr, SSZ, 1.0f);
}

// round 11
// speedup vs baseline: 1.0001x; 1.0001x over previous
#include <cuda_runtime.h>
#include <cuda_bf16.h>
#include <math.h>
#include <stdint.h>
#include <stddef.h>

// ============================================================================
// biSoftmax on GB300 via HMMA (mma.sync bf16) split-precision GEMMs.
// R11: term-major MMA ordering -- each accumulator's three split-products are
//      issued 16 MMAs apart (was 4), breaking the HMMA RAW-latency stall that
//      pinned tensor% at ~55 across four pipeline configs. GEMM config back to
//      R8's best (128x128 CTA, 256 thr, 3-stage, 2 CTAs/SM). Keeps R10's
//      fused circle GEMM (score1-score2 via [A1|A2] @ [W1|-W2]^T, squared).
// All GEMMs are NT: C[m,n] = alpha * sum_k A[m,k] * B[n,k]
// fp32 operands stored as bf16 (hi,lo); accumulate Ahi*Bhi + Ahi*Blo + Alo*Bhi.
// ============================================================================

#define SEQ 2048
#define NH 8
#define MROWS (NH * SEQ)                 // 16384
#define SSZ ((size_t)SEQ * SEQ)          // 2^22
#define NTOT ((size_t)MROWS * SEQ)       // 2^25

typedef __nv_bfloat16 bf16;

// ---------------- scratch (device globals, allocation-free) ----------------
__device__ bf16 g_xh[NTOT],       g_xl[NTOT];
__device__ bf16 g_Wvh[SSZ],       g_Wvl[SSZ];        // Wv
__device__ bf16 g_Wch[2 * SSZ],   g_Wcl[2 * SSZ];    // Wcat = [W1 | -W2], ld 4096
__device__ bf16 g_WTqh[2 * SSZ],  g_WTql[2 * SSZ];   // Wq1^T, Wq2^T
__device__ bf16 g_WTkh[2 * SSZ],  g_WTkl[2 * SSZ];   // Wk1^T, Wk2^T
__device__ bf16 g_Nh[2 * SSZ],    g_Nl[2 * SSZ];     // N_i = Wk_i^T Wq_i
__device__ bf16 g_Th[2 * NTOT],   g_Tl[2 * NTOT];    // T_i = X N_i^T
__device__ bf16 g_Vth[NTOT],      g_Vtl[NTOT];       // [h][e][t]
__device__ bf16 g_Ah[2 * NTOT],   g_Al[2 * NTOT];    // Acat: [h*S+s][4096]
__device__ bf16 g_Ch[NTOT],       g_Cl[NTOT];        // circle
__device__ float g_S[2 * NTOT];                      // logits (fp32)

// ---------------- PTX helpers ----------------
__device__ __forceinline__ uint32_t smem_u32(const void* p) {
    uint32_t a;
    asm("{ .reg .u64 t; cvta.to.shared.u64 t, %1; cvt.u32.u64 %0, t; }" : "=r"(a) : "l"(p));
    return a;
}

#define CP16(dst, src) \
    asm volatile("cp.async.cg.shared.global [%0], [%1], 16;" :: "r"(dst), "l"(src) : "memory")
#define CP_COMMIT() asm volatile("cp.async.commit_group;" ::: "memory")
#define CP_WAIT1()  asm volatile("cp.async.wait_group 1;" ::: "memory")

#define LDSM4(r0, r1, r2, r3, a) \
    asm volatile("ldmatrix.sync.aligned.m8n8.x4.shared.b16 {%0,%1,%2,%3}, [%4];" \
        : "=r"(r0), "=r"(r1), "=r"(r2), "=r"(r3) : "r"(a))

#define MMA_BF16(d, a, b) \
    asm volatile("mma.sync.aligned.m16n8k16.row.col.f32.bf16.bf16.f32 " \
        "{%0,%1,%2,%3}, {%4,%5,%6,%7}, {%8,%9}, {%0,%1,%2,%3};" \
        : "+f"((d)[0]), "+f"((d)[1]), "+f"((d)[2]), "+f"((d)[3]) \
        : "r"((a)[0]), "r"((a)[1]), "r"((a)[2]), "r"((a)[3]), "r"((b)[0]), "r"((b)[1]))

// ---------------- HMMA split-precision GEMM ----------------
// CTA tile 128x128, BK=32, 3 stages, 256 threads (8 warps of 64x32), 2 CTAs/SM.
// smem row = 32 bf16 = 64B packed; chunk c of row r at r*64+((c^((r>>1)&3))<<4).
// Stage: Ahi[0,8K) Alo[8K,16K) Bhi[16K,24K) Blo[24K,32K)
static constexpr int STAGE_B = 32768;
static constexpr int SMEM_HG = 3 * STAGE_B;   // 98304 -> 2 CTAs/SM (192KB)

// z decomposition: zi = z>>3, zr = z&7; row offsets = zi*Hi + zr*Lo
// EPI: 0 = fp32 * alpha, 1 = bf16 (hi,lo) pair, 2 = square -> bf16 pair
template <int EPI>
__global__ __launch_bounds__(256, 2)
void hgemm3(const bf16* __restrict__ Ah, const bf16* __restrict__ Al,
            const bf16* __restrict__ Bh, const bf16* __restrict__ Bl,
            float* __restrict__ Cf, bf16* __restrict__ Ch, bf16* __restrict__ Cl,
            int K, int ldc, size_t sC,
            int azHi, int azLo, int bzHi, int bzLo, float alpha)
{
    extern __shared__ char smem[];
    const uint32_t sbase = smem_u32(smem);
    const int tid  = threadIdx.x;
    const int lane = tid & 31;
    const int wid  = tid >> 5;
    const int wm   = wid >> 2;          // 0..1 -> 64-row slab
    const int wn   = wid & 3;           // 0..3 -> 32-col slab
    const int row0 = blockIdx.y * 128;
    const int col0 = blockIdx.x * 128;
    const int z    = blockIdx.z;
    const int zi   = z >> 3, zr = z & 7;
    const int aoff = zi * azHi + zr * azLo;
    const int boff = zi * bzHi + zr * bzLo;

    // ---- loader lanes: 256 threads, each 2x16B per buffer per stage ----
    const int lr  = tid >> 1;           // 0..127 row
    const int lcb = (tid & 1) * 2;      // chunk 0 or 2
    const size_t arow = (size_t)(row0 + aoff + lr);
    const size_t brow = (size_t)(col0 + boff + lr);
    const bf16* pAh = Ah + arow * K + lcb * 8;
    const bf16* pAl = Al + arow * K + lcb * 8;
    const bf16* pBh = Bh + brow * K + lcb * 8;
    const bf16* pBl = Bl + brow * K + lcb * 8;
    const uint32_t lsw = (uint32_t)((lr >> 1) & 3);
    const uint32_t st1 = lr * 64 + (((uint32_t)lcb ^ lsw) << 4);
    const uint32_t st2 = lr * 64 + ((((uint32_t)lcb + 1u) ^ lsw) << 4);

    auto prefetch = [&](int go, int stage) {
        const uint32_t sb = sbase + (uint32_t)stage * STAGE_B;
        CP16(sb +          st1, pAh + go); CP16(sb +          st2, pAh + go + 8);
        CP16(sb +  8192u + st1, pAl + go); CP16(sb +  8192u + st2, pAl + go + 8);
        CP16(sb + 16384u + st1, pBh + go); CP16(sb + 16384u + st2, pBh + go + 8);
        CP16(sb + 24576u + st1, pBl + go); CP16(sb + 24576u + st2, pBl + go + 8);
    };

    // ---- fragment addressing ----
    const int lr16  = lane & 15;
    const uint32_t khalf = (uint32_t)(lane >> 4);
    const uint32_t fsw   = (uint32_t)((lr16 >> 1) & 3);
    uint32_t a_base[4], b_base[2];
    #pragma unroll
    for (int mi = 0; mi < 4; mi++) a_base[mi] = (uint32_t)(wm * 64 + mi * 16 + lr16) * 64u;
    #pragma unroll
    for (int g = 0; g < 2; g++)    b_base[g]  = (uint32_t)(wn * 32 + g * 16 + lr16) * 64u;

    float acc[4][4][4];
    #pragma unroll
    for (int mi = 0; mi < 4; mi++)
        #pragma unroll
        for (int nj = 0; nj < 4; nj++)
            #pragma unroll
            for (int q = 0; q < 4; q++) acc[mi][nj][q] = 0.0f;

    const int nk = K >> 5;

    prefetch(0, 0);  CP_COMMIT();
    prefetch(32, 1); CP_COMMIT();

    int cs = 0;           // compute stage
    int ps = 2;           // prefetch stage
    int gof = 64;         // next global k-offset to fetch
    for (int kt = 0; kt < nk; kt++) {
        CP_WAIT1();
        __syncthreads();

        // stage ps == (kt+2)%3 was fully consumed before the sync above.
        if (kt + 2 < nk) { prefetch(gof, ps); gof += 32; }
        CP_COMMIT();

        const uint32_t stg = sbase + (uint32_t)cs * STAGE_B;
        #pragma unroll
        for (int ks = 0; ks < 2; ks++) {
            const uint32_t coff = ((((uint32_t)(ks * 2) + khalf) ^ fsw) << 4);
            // B fragments (hi+lo) and Ahi for ALL mi -> term-major MMA order:
            // every acc[mi][nj] is revisited at distance 16 (was 4).
            uint32_t Bhi[4][2], Blo[4][2];
            #pragma unroll
            for (int g = 0; g < 2; g++) {
                uint32_t q0, q1, q2, q3;
                LDSM4(q0, q1, q2, q3, stg + 16384u + b_base[g] + coff);
                Bhi[2 * g][0] = q0;     Bhi[2 * g][1] = q2;
                Bhi[2 * g + 1][0] = q1; Bhi[2 * g + 1][1] = q3;
                LDSM4(q0, q1, q2, q3, stg + 24576u + b_base[g] + coff);
                Blo[2 * g][0] = q0;     Blo[2 * g][1] = q2;
                Blo[2 * g + 1][0] = q1; Blo[2 * g + 1][1] = q3;
            }
            uint32_t Ahi[4][4];
            #pragma unroll
            for (int mi = 0; mi < 4; mi++)
                LDSM4(Ahi[mi][0], Ahi[mi][1], Ahi[mi][2], Ahi[mi][3],
                      stg + a_base[mi] + coff);

            // term 1: Ahi * Bhi
            #pragma unroll
            for (int mi = 0; mi < 4; mi++)
                #pragma unroll
                for (int nj = 0; nj < 4; nj++)
                    MMA_BF16(acc[mi][nj], Ahi[mi], Bhi[nj]);
            // term 2: Ahi * Blo
            #pragma unroll
            for (int mi = 0; mi < 4; mi++)
                #pragma unroll
                for (int nj = 0; nj < 4; nj++)
                    MMA_BF16(acc[mi][nj], Ahi[mi], Blo[nj]);
            // term 3: Alo * Bhi (Alo loaded per-mi; each acc still touched
            // exactly once per term -> reuse distance stays 16)
            #pragma unroll
            for (int mi = 0; mi < 4; mi++) {
                uint32_t Alo[4];
                LDSM4(Alo[0], Alo[1], Alo[2], Alo[3],
                      stg + 8192u + a_base[mi] + coff);
                #pragma unroll
                for (int nj = 0; nj < 4; nj++)
                    MMA_BF16(acc[mi][nj], Alo, Bhi[nj]);
            }
        }

        cs = (cs == 2) ? 0 : cs + 1;
        ps = (ps == 2) ? 0 : ps + 1;
    }

    // ---- epilogue ----
    const size_t cb = (size_t)z * sC;
    #pragma unroll
    for (int mi = 0; mi < 4; mi++) {
        #pragma unroll
        for (int nj = 0; nj < 4; nj++) {
            const int rg = row0 + wm * 64 + mi * 16 + (lane >> 2);
            const int cg = col0 + wn * 32 + nj * 8 + (lane & 3) * 2;
            float d0 = acc[mi][nj][0] * alpha, d1 = acc[mi][nj][1] * alpha;
            float d2 = acc[mi][nj][2] * alpha, d3 = acc[mi][nj][3] * alpha;
            if (EPI == 2) { d0 *= d0; d1 *= d1; d2 *= d2; d3 *= d3; }
            const size_t i0 = cb + (size_t)rg * ldc + cg;
            const size_t i1 = cb + (size_t)(rg + 8) * ldc + cg;
            if (EPI == 0) {
                *(float2*)(Cf + i0) = make_float2(d0, d1);
                *(float2*)(Cf + i1) = make_float2(d2, d3);
            } else {
                __nv_bfloat162 h, l;
                h.x = __float2bfloat16(d0);
                h.y = __float2bfloat16(d1);
                l.x = __float2bfloat16(d0 - __bfloat162float(h.x));
                l.y = __float2bfloat16(d1 - __bfloat162float(h.y));
                *(__nv_bfloat162*)(Ch + i0) = h;
                *(__nv_bfloat162*)(Cl + i0) = l;
                h.x = __float2bfloat16(d2);
                h.y = __float2bfloat16(d3);
                l.x = __float2bfloat16(d2 - __bfloat162float(h.x));
                l.y = __float2bfloat16(d3 - __bfloat162float(h.y));
                *(__nv_bfloat162*)(Ch + i1) = h;
                *(__nv_bfloat162*)(Cl + i1) = l;
            }
        }
    }
}

// ---------------- conversions ----------------
struct WPtrs3 { const float* p[3]; };   // Wv, W1, W2
struct WPtrs4 { const float* p[4]; };   // Wq1, Wk1, Wq2, Wk2

// y==0: x -> pair. y==1: Wv -> pair; Wcat=[W1|-W2] (ld 4096) -> pair.
__global__ __launch_bounds__(256)
void convert_all(const float* __restrict__ x, WPtrs3 w,
                 bf16* __restrict__ xh, bf16* __restrict__ xl,
                 bf16* __restrict__ Wvh, bf16* __restrict__ Wvl,
                 bf16* __restrict__ Wch, bf16* __restrict__ Wcl)
{
    const size_t stride = (size_t)gridDim.x * blockDim.x;
    size_t i = (size_t)blockIdx.x * blockDim.x + threadIdx.x;
    if (blockIdx.y == 0) {
        for (; i < NTOT; i += stride) {
            float f = x[i];
            bf16 h = __float2bfloat16(f);
            xh[i] = h;
            xl[i] = __float2bfloat16(f - __bfloat162float(h));
        }
    } else {
        const size_t n = 3 * SSZ;
        for (; i < n; i += stride) {
            if (i < SSZ) {
                float f = w.p[0][i];
                bf16 h = __float2bfloat16(f);
                Wvh[i] = h;
                Wvl[i] = __float2bfloat16(f - __bfloat162float(h));
            } else {
                const size_t j = i - SSZ;
                const size_t u = j >> 12;          // row (4096 cols)
                const int k = (int)(j & 4095);
                float f = (k < SEQ) ? w.p[1][u * SEQ + k]
                                    : -w.p[2][u * SEQ + (k - SEQ)];
                bf16 h = __float2bfloat16(f);
                Wch[j] = h;
                Wcl[j] = __float2bfloat16(f - __bfloat162float(h));
            }
        }
    }
}

// Transpose Wq1,Wk1,Wq2,Wk2 (fp32 [SEQ,SEQ]) -> bf16 (hi,lo) pairs.
__global__ __launch_bounds__(256)
void transpose_pairs(WPtrs4 w,
                     bf16* __restrict__ WTqh, bf16* __restrict__ WTql,
                     bf16* __restrict__ WTkh, bf16* __restrict__ WTkl)
{
    __shared__ float t[32][33];
    const int z = blockIdx.z;
    const float* src = w.p[z];
    bf16* dh = (z & 1) ? WTkh : WTqh;
    bf16* dl = (z & 1) ? WTkl : WTql;
    const size_t base = (z >> 1) ? SSZ : 0;

    const int tx = threadIdx.x, ty = threadIdx.y;   // 32 x 8
    const int x = blockIdx.x * 32 + tx;
    const int y = blockIdx.y * 32 + ty;
    #pragma unroll
    for (int r = 0; r < 4; r++)
        t[ty + r * 8][tx] = src[(size_t)(y + r * 8) * SEQ + x];
    __syncthreads();
    const int x2 = blockIdx.y * 32 + tx;
    const int y2 = blockIdx.x * 32 + ty;
    #pragma unroll
    for (int r = 0; r < 4; r++) {
        float f = t[tx][ty + r * 8];
        bf16 h = __float2bfloat16(f);
        const size_t idx = base + (size_t)(y2 + r * 8) * SEQ + x2;
        dh[idx] = h;
        dl[idx] = __float2bfloat16(f - __bfloat162float(h));
    }
}

// softmax of S row r (r in [0, 2*MROWS)); writes into Acat[h*S+s][i*2048 + :]
__global__ __launch_bounds__(256)
void softmax_cat(const float* __restrict__ S, bf16* __restrict__ Ph,
                 bf16* __restrict__ Pl)
{
    const int tid = threadIdx.x;
    const int r = blockIdx.x;
    const int branch = r >> 14;           // 0 or 1 (MROWS = 2^14)
    const int hs = r & (MROWS - 1);
    const float* p = S + (size_t)r * SEQ;
    const size_t dst = (size_t)hs * 4096 + (size_t)branch * SEQ;
    bf16* oh = Ph + dst;
    bf16* ol = Pl + dst;
    __shared__ float buf[SEQ];
    __shared__ float red[256];

    float m = -INFINITY;
    for (int i = tid; i < SEQ; i += 256) { float v = p[i]; buf[i] = v; m = fmaxf(m, v); }
    red[tid] = m; __syncthreads();
    for (int s = 128; s > 0; s >>= 1) { if (tid < s) red[tid] = fmaxf(red[tid], red[tid + s]); __syncthreads(); }
    m = red[0]; __syncthreads();

    float sum = 0.0f;
    for (int i = tid; i < SEQ; i += 256) { float e = __expf(buf[i] - m); buf[i] = e; sum += e; }
    red[tid] = sum; __syncthreads();
    for (int s = 128; s > 0; s >>= 1) { if (tid < s) red[tid] += red[tid + s]; __syncthreads(); }
    const float inv = 1.0f / red[0]; __syncthreads();

    for (int i = tid; i < SEQ; i += 256) {
        float f = buf[i] * inv;
        bf16 h = __float2bfloat16(f);
        oh[i] = h;
        ol[i] = __float2bfloat16(f - __bfloat162float(h));
    }
}

// ---------------- host side ----------------
template <typename T>
static T* sym_addr(T* symbol) {
    void* p = nullptr;
    cudaGetSymbolAddress(&p, (const void*)symbol);
    return (T*)p;
}

// Mrows multiple of 128; K multiple of 2048; lda = ldb = K.
static void run_hgemm(const bf16* Ah, const bf16* Al, int azHi, int azLo,
                      const bf16* Bh, const bf16* Bl, int bzHi, int bzLo,
                      int Mrows, int Ncols, int K, int ldc, int batch, int epi,
                      float* Cf, bf16* Ch, bf16* Cl, size_t sC, float alpha)
{
    dim3 grid(Ncols / 128, Mrows / 128, batch);
    if (epi == 0)
        hgemm3<0><<<grid, 256, SMEM_HG>>>(Ah, Al, Bh, Bl, Cf, Ch, Cl,
                                          K, ldc, sC, azHi, azLo, bzHi, bzLo, alpha);
    else if (epi == 1)
        hgemm3<1><<<grid, 256, SMEM_HG>>>(Ah, Al, Bh, Bl, Cf, Ch, Cl,
                                          K, ldc, sC, azHi, azLo, bzHi, bzLo, alpha);
    else
        hgemm3<2><<<grid, 256, SMEM_HG>>>(Ah, Al, Bh, Bl, Cf, Ch, Cl,
                                          K, ldc, sC, azHi, azLo, bzHi, bzLo, alpha);
}

extern "C" void kernel_launch(void* const* d_in, const int* in_sizes, int n_in,
                              void* d_out, int out_size)
{
    (void)in_sizes; (void)n_in; (void)out_size;
    const float* x = (const float*)d_in[0];
    WPtrs4 wqk;
    wqk.p[0] = (const float*)d_in[1];   // Wq1
    wqk.p[1] = (const float*)d_in[2];   // Wk1
    wqk.p[2] = (const float*)d_in[3];   // Wq2
    wqk.p[3] = (const float*)d_in[4];   // Wk2
    WPtrs3 wv;
    wv.p[0] = (const float*)d_in[5];    // Wv
    wv.p[1] = (const float*)d_in[6];    // W1
    wv.p[2] = (const float*)d_in[7];    // W2
    float* out = (float*)d_out;

    cudaFuncSetAttribute((const void*)hgemm3<0>,
                         cudaFuncAttributeMaxDynamicSharedMemorySize, SMEM_HG);
    cudaFuncSetAttribute((const void*)hgemm3<1>,
                         cudaFuncAttributeMaxDynamicSharedMemorySize, SMEM_HG);
    cudaFuncSetAttribute((const void*)hgemm3<2>,
                         cudaFuncAttributeMaxDynamicSharedMemorySize, SMEM_HG);

    bf16 *xh = sym_addr(g_xh),   *xl = sym_addr(g_xl);
    bf16 *Wvh = sym_addr(g_Wvh), *Wvl = sym_addr(g_Wvl);
    bf16 *Wch = sym_addr(g_Wch), *Wcl = sym_addr(g_Wcl);
    bf16 *WTqh = sym_addr(g_WTqh), *WTql = sym_addr(g_WTql);
    bf16 *WTkh = sym_addr(g_WTkh), *WTkl = sym_addr(g_WTkl);
    bf16 *Nhh = sym_addr(g_Nh),  *Nll = sym_addr(g_Nl);
    bf16 *Thh = sym_addr(g_Th),  *Tll = sym_addr(g_Tl);
    bf16 *Vth = sym_addr(g_Vth), *Vtl = sym_addr(g_Vtl);
    bf16 *Ahh = sym_addr(g_Ah),  *All = sym_addr(g_Al);
    bf16 *Chh = sym_addr(g_Ch),  *Cll = sym_addr(g_Cl);
    float *S = sym_addr(g_S);

    const float scale = 1.0f / sqrtf((float)SEQ);

    // [0] conversions: x, Wv, Wcat=[W1|-W2]
    convert_all<<<dim3(1024, 2), 256>>>(x, wv, xh, xl, Wvh, Wvl, Wch, Wcl);

    // [1] transposes: Wq1,Wk1,Wq2,Wk2 -> WTq/WTk bf16 pairs
    transpose_pairs<<<dim3(SEQ / 32, SEQ / 32, 4), dim3(32, 8)>>>(
        wqk, WTqh, WTql, WTkh, WTkl);

    // [2] N_i = WTk_i @ WTq_i^T   (z = i, 2 batches)
    run_hgemm(WTkh, WTkl, 0, SEQ, WTqh, WTql, 0, SEQ,
              SEQ, SEQ, SEQ, SEQ, 2, 1, nullptr, Nhh, Nll, SSZ, 1.0f);

    // [3] T_i = X @ N_i^T   (z = i, full M = 16384)
    run_hgemm(xh, xl, 0, 0, Nhh, Nll, 0, SEQ,
              MROWS, SEQ, SEQ, SEQ, 2, 1, nullptr, Thh, Tll, NTOT, 1.0f);

    // [4] Vt[h] = Wv @ X[h]^T   (z = head)
    run_hgemm(Wvh, Wvl, 0, 0, xh, xl, 0, SEQ,
              SEQ, SEQ, SEQ, SEQ, NH, 1, nullptr, Vth, Vtl, SSZ, 1.0f);

    // [5] logits: S[i][h] = scale * T_i[h] @ X[h]^T   (z = i*8+h, 16 batches)
    run_hgemm(Thh, Tll, MROWS, SEQ, xh, xl, 0, SEQ,
              SEQ, SEQ, SEQ, SEQ, 2 * NH, 0, S, nullptr, nullptr, SSZ, scale);

    // [6] softmax rows -> Acat bf16 pairs ([h*S+s][branch*2048 + :], ld 4096)
    softmax_cat<<<2 * MROWS, 256>>>(S, Ahh, All);

    // [7] circle[h] = (Acat[h] @ Wcat^T)^2  -- K=4096, squared epilogue
    run_hgemm(Ahh, All, 0, SEQ, Wch, Wcl, 0, 0,
              SEQ, SEQ, 2 * SEQ, SEQ, NH, 2, nullptr, Chh, Cll, SSZ, 1.0f);

    // [8] out[h] = circle[h] @ Vt[h]^T -> fp32
    run_hgemm(Chh, Cll, 0, SEQ, Vth, Vtl, 0, SEQ,
              SEQ, SEQ, SEQ, SEQ, NH, 0, out, nullptr, nullptr, SSZ, 1.0f);
}

// round 12
// speedup vs baseline: 1.0404x; 1.0403x over previous
#include <cuda_runtime.h>
#include <cuda_bf16.h>
#include <math.h>
#include <stdint.h>
#include <stddef.h>

// ============================================================================
// biSoftmax on GB300 via HMMA (mma.sync bf16) split-precision GEMMs.
// R12: de-phased mainloop -- warp halves process the two 16-k slices in
//      OPPOSITE order (0,1 vs 1,0) so LDSM bursts of one half overlap MMA
//      bursts of the other; cp.async prefetch issued BETWEEN the slices
//      instead of colliding with the post-barrier LDSM storm.
// All GEMMs are NT: C[m,n] = alpha * sum_k A[m,k] * B[n,k]
// fp32 operands stored as bf16 (hi,lo); accumulate Ahi*Bhi + Ahi*Blo + Alo*Bhi.
// ============================================================================

#define SEQ 2048
#define NH 8
#define MROWS (NH * SEQ)                 // 16384
#define SSZ ((size_t)SEQ * SEQ)          // 2^22
#define NTOT ((size_t)MROWS * SEQ)       // 2^25

typedef __nv_bfloat16 bf16;

// ---------------- scratch (device globals, allocation-free) ----------------
__device__ bf16 g_xh[NTOT],       g_xl[NTOT];
__device__ bf16 g_Wvh[SSZ],       g_Wvl[SSZ];        // Wv
__device__ bf16 g_Wch[2 * SSZ],   g_Wcl[2 * SSZ];    // Wcat = [W1 | -W2], ld 4096
__device__ bf16 g_WTqh[2 * SSZ],  g_WTql[2 * SSZ];   // Wq1^T, Wq2^T
__device__ bf16 g_WTkh[2 * SSZ],  g_WTkl[2 * SSZ];   // Wk1^T, Wk2^T
__device__ bf16 g_Nh[2 * SSZ],    g_Nl[2 * SSZ];     // N_i = Wk_i^T Wq_i
__device__ bf16 g_Th[2 * NTOT],   g_Tl[2 * NTOT];    // T_i = X N_i^T
__device__ bf16 g_Vth[NTOT],      g_Vtl[NTOT];       // [h][e][t]
__device__ bf16 g_Ah[2 * NTOT],   g_Al[2 * NTOT];    // Acat: [h*S+s][4096]
__device__ bf16 g_Ch[NTOT],       g_Cl[NTOT];        // circle
__device__ float g_S[2 * NTOT];                      // logits (fp32)

// ---------------- PTX helpers ----------------
__device__ __forceinline__ uint32_t smem_u32(const void* p) {
    uint32_t a;
    asm("{ .reg .u64 t; cvta.to.shared.u64 t, %1; cvt.u32.u64 %0, t; }" : "=r"(a) : "l"(p));
    return a;
}

#define CP16(dst, src) \
    asm volatile("cp.async.cg.shared.global [%0], [%1], 16;" :: "r"(dst), "l"(src) : "memory")
#define CP_COMMIT() asm volatile("cp.async.commit_group;" ::: "memory")
#define CP_WAIT1()  asm volatile("cp.async.wait_group 1;" ::: "memory")

#define LDSM4(r0, r1, r2, r3, a) \
    asm volatile("ldmatrix.sync.aligned.m8n8.x4.shared.b16 {%0,%1,%2,%3}, [%4];" \
        : "=r"(r0), "=r"(r1), "=r"(r2), "=r"(r3) : "r"(a))

#define MMA_BF16(d, a, b) \
    asm volatile("mma.sync.aligned.m16n8k16.row.col.f32.bf16.bf16.f32 " \
        "{%0,%1,%2,%3}, {%4,%5,%6,%7}, {%8,%9}, {%0,%1,%2,%3};" \
        : "+f"((d)[0]), "+f"((d)[1]), "+f"((d)[2]), "+f"((d)[3]) \
        : "r"((a)[0]), "r"((a)[1]), "r"((a)[2]), "r"((a)[3]), "r"((b)[0]), "r"((b)[1]))

// ---------------- HMMA split-precision GEMM ----------------
// CTA tile 128x128, BK=32, 3 stages, 256 threads (8 warps of 64x32), 2 CTAs/SM.
// smem row = 32 bf16 = 64B packed; chunk c of row r at r*64+((c^((r>>1)&3))<<4).
// Stage: Ahi[0,8K) Alo[8K,16K) Bhi[16K,24K) Blo[24K,32K)
static constexpr int STAGE_B = 32768;
static constexpr int SMEM_HG = 3 * STAGE_B;   // 98304 -> 2 CTAs/SM (192KB)

// z decomposition: zi = z>>3, zr = z&7; row offsets = zi*Hi + zr*Lo
// EPI: 0 = fp32 * alpha, 1 = bf16 (hi,lo) pair, 2 = square -> bf16 pair
template <int EPI>
__global__ __launch_bounds__(256, 2)
void hgemm3(const bf16* __restrict__ Ah, const bf16* __restrict__ Al,
            const bf16* __restrict__ Bh, const bf16* __restrict__ Bl,
            float* __restrict__ Cf, bf16* __restrict__ Ch, bf16* __restrict__ Cl,
            int K, int ldc, size_t sC,
            int azHi, int azLo, int bzHi, int bzLo, float alpha)
{
    extern __shared__ char smem[];
    const uint32_t sbase = smem_u32(smem);
    const int tid  = threadIdx.x;
    const int lane = tid & 31;
    const int wid  = tid >> 5;
    const int wm   = wid >> 2;          // 0..1 -> 64-row slab
    const int wn   = wid & 3;           // 0..3 -> 32-col slab
    const int khog = (wid >> 1) & 1;    // warp-half phase: 0 -> (0,1), 1 -> (1,0)
    const int row0 = blockIdx.y * 128;
    const int col0 = blockIdx.x * 128;
    const int z    = blockIdx.z;
    const int zi   = z >> 3, zr = z & 7;
    const int aoff = zi * azHi + zr * azLo;
    const int boff = zi * bzHi + zr * bzLo;

    // ---- loader lanes: 256 threads, each 2x16B per buffer per stage ----
    const int lr  = tid >> 1;           // 0..127 row
    const int lcb = (tid & 1) * 2;      // chunk 0 or 2
    const size_t arow = (size_t)(row0 + aoff + lr);
    const size_t brow = (size_t)(col0 + boff + lr);
    const bf16* pAh = Ah + arow * K + lcb * 8;
    const bf16* pAl = Al + arow * K + lcb * 8;
    const bf16* pBh = Bh + brow * K + lcb * 8;
    const bf16* pBl = Bl + brow * K + lcb * 8;
    const uint32_t lsw = (uint32_t)((lr >> 1) & 3);
    const uint32_t st1 = lr * 64 + (((uint32_t)lcb ^ lsw) << 4);
    const uint32_t st2 = lr * 64 + ((((uint32_t)lcb + 1u) ^ lsw) << 4);

    auto prefetch = [&](int go, int stage) {
        const uint32_t sb = sbase + (uint32_t)stage * STAGE_B;
        CP16(sb +          st1, pAh + go); CP16(sb +          st2, pAh + go + 8);
        CP16(sb +  8192u + st1, pAl + go); CP16(sb +  8192u + st2, pAl + go + 8);
        CP16(sb + 16384u + st1, pBh + go); CP16(sb + 16384u + st2, pBh + go + 8);
        CP16(sb + 24576u + st1, pBl + go); CP16(sb + 24576u + st2, pBl + go + 8);
    };

    // ---- fragment addressing ----
    const int lr16  = lane & 15;
    const uint32_t khalf = (uint32_t)(lane >> 4);
    const uint32_t fsw   = (uint32_t)((lr16 >> 1) & 3);
    uint32_t a_base[4], b_base[2];
    #pragma unroll
    for (int mi = 0; mi < 4; mi++) a_base[mi] = (uint32_t)(wm * 64 + mi * 16 + lr16) * 64u;
    #pragma unroll
    for (int g = 0; g < 2; g++)    b_base[g]  = (uint32_t)(wn * 32 + g * 16 + lr16) * 64u;

    float acc[4][4][4];
    #pragma unroll
    for (int mi = 0; mi < 4; mi++)
        #pragma unroll
        for (int nj = 0; nj < 4; nj++)
            #pragma unroll
            for (int q = 0; q < 4; q++) acc[mi][nj][q] = 0.0f;

    // one 16-k slice, term-major MMA order
    auto slice = [&](uint32_t stg, int ks) {
        const uint32_t coff = ((((uint32_t)(ks * 2) + khalf) ^ fsw) << 4);
        uint32_t Bhi[4][2], Blo[4][2];
        #pragma unroll
        for (int g = 0; g < 2; g++) {
            uint32_t q0, q1, q2, q3;
            LDSM4(q0, q1, q2, q3, stg + 16384u + b_base[g] + coff);
            Bhi[2 * g][0] = q0;     Bhi[2 * g][1] = q2;
            Bhi[2 * g + 1][0] = q1; Bhi[2 * g + 1][1] = q3;
            LDSM4(q0, q1, q2, q3, stg + 24576u + b_base[g] + coff);
            Blo[2 * g][0] = q0;     Blo[2 * g][1] = q2;
            Blo[2 * g + 1][0] = q1; Blo[2 * g + 1][1] = q3;
        }
        uint32_t Ahi[4][4];
        #pragma unroll
        for (int mi = 0; mi < 4; mi++)
            LDSM4(Ahi[mi][0], Ahi[mi][1], Ahi[mi][2], Ahi[mi][3],
                  stg + a_base[mi] + coff);

        #pragma unroll
        for (int mi = 0; mi < 4; mi++)
            #pragma unroll
            for (int nj = 0; nj < 4; nj++)
                MMA_BF16(acc[mi][nj], Ahi[mi], Bhi[nj]);
        #pragma unroll
        for (int mi = 0; mi < 4; mi++)
            #pragma unroll
            for (int nj = 0; nj < 4; nj++)
                MMA_BF16(acc[mi][nj], Ahi[mi], Blo[nj]);
        #pragma unroll
        for (int mi = 0; mi < 4; mi++) {
            uint32_t Alo[4];
            LDSM4(Alo[0], Alo[1], Alo[2], Alo[3],
                  stg + 8192u + a_base[mi] + coff);
            #pragma unroll
            for (int nj = 0; nj < 4; nj++)
                MMA_BF16(acc[mi][nj], Alo, Bhi[nj]);
        }
    };

    const int nk = K >> 5;

    prefetch(0, 0);  CP_COMMIT();
    prefetch(32, 1); CP_COMMIT();

    int cs = 0;           // compute stage
    int ps = 2;           // prefetch stage
    int gof = 64;         // next global k-offset to fetch
    for (int kt = 0; kt < nk; kt++) {
        CP_WAIT1();
        __syncthreads();

        const uint32_t stg = sbase + (uint32_t)cs * STAGE_B;

        // warp-half 0 does slice 0 now; warp-half 1 does slice 1 -> at any
        // instant half the warps LDSM while the other half issues MMAs.
        slice(stg, khog);

        // prefetch between the slices (port pressure spread across the kstep)
        if (kt + 2 < nk) { prefetch(gof, ps); gof += 32; }
        CP_COMMIT();

        slice(stg, 1 - khog);

        cs = (cs == 2) ? 0 : cs + 1;
        ps = (ps == 2) ? 0 : ps + 1;
    }

    // ---- epilogue ----
    const size_t cb = (size_t)z * sC;
    #pragma unroll
    for (int mi = 0; mi < 4; mi++) {
        #pragma unroll
        for (int nj = 0; nj < 4; nj++) {
            const int rg = row0 + wm * 64 + mi * 16 + (lane >> 2);
            const int cg = col0 + wn * 32 + nj * 8 + (lane & 3) * 2;
            float d0 = acc[mi][nj][0] * alpha, d1 = acc[mi][nj][1] * alpha;
            float d2 = acc[mi][nj][2] * alpha, d3 = acc[mi][nj][3] * alpha;
            if (EPI == 2) { d0 *= d0; d1 *= d1; d2 *= d2; d3 *= d3; }
            const size_t i0 = cb + (size_t)rg * ldc + cg;
            const size_t i1 = cb + (size_t)(rg + 8) * ldc + cg;
            if (EPI == 0) {
                *(float2*)(Cf + i0) = make_float2(d0, d1);
                *(float2*)(Cf + i1) = make_float2(d2, d3);
            } else {
                __nv_bfloat162 h, l;
                h.x = __float2bfloat16(d0);
                h.y = __float2bfloat16(d1);
                l.x = __float2bfloat16(d0 - __bfloat162float(h.x));
                l.y = __float2bfloat16(d1 - __bfloat162float(h.y));
                *(__nv_bfloat162*)(Ch + i0) = h;
                *(__nv_bfloat162*)(Cl + i0) = l;
                h.x = __float2bfloat16(d2);
                h.y = __float2bfloat16(d3);
                l.x = __float2bfloat16(d2 - __bfloat162float(h.x));
                l.y = __float2bfloat16(d3 - __bfloat162float(h.y));
                *(__nv_bfloat162*)(Ch + i1) = h;
                *(__nv_bfloat162*)(Cl + i1) = l;
            }
        }
    }
}

// ---------------- conversions ----------------
struct WPtrs3 { const float* p[3]; };   // Wv, W1, W2
struct WPtrs4 { const float* p[4]; };   // Wq1, Wk1, Wq2, Wk2

// y==0: x -> pair. y==1: Wv -> pair; Wcat=[W1|-W2] (ld 4096) -> pair.
__global__ __launch_bounds__(256)
void convert_all(const float* __restrict__ x, WPtrs3 w,
                 bf16* __restrict__ xh, bf16* __restrict__ xl,
                 bf16* __restrict__ Wvh, bf16* __restrict__ Wvl,
                 bf16* __restrict__ Wch, bf16* __restrict__ Wcl)
{
    const size_t stride = (size_t)gridDim.x * blockDim.x;
    size_t i = (size_t)blockIdx.x * blockDim.x + threadIdx.x;
    if (blockIdx.y == 0) {
        for (; i < NTOT; i += stride) {
            float f = x[i];
            bf16 h = __float2bfloat16(f);
            xh[i] = h;
            xl[i] = __float2bfloat16(f - __bfloat162float(h));
        }
    } else {
        const size_t n = 3 * SSZ;
        for (; i < n; i += stride) {
            if (i < SSZ) {
                float f = w.p[0][i];
                bf16 h = __float2bfloat16(f);
                Wvh[i] = h;
                Wvl[i] = __float2bfloat16(f - __bfloat162float(h));
            } else {
                const size_t j = i - SSZ;
                const size_t u = j >> 12;          // row (4096 cols)
                const int k = (int)(j & 4095);
                float f = (k < SEQ) ? w.p[1][u * SEQ + k]
                                    : -w.p[2][u * SEQ + (k - SEQ)];
                bf16 h = __float2bfloat16(f);
                Wch[j] = h;
                Wcl[j] = __float2bfloat16(f - __bfloat162float(h));
            }
        }
    }
}

// Transpose Wq1,Wk1,Wq2,Wk2 (fp32 [SEQ,SEQ]) -> bf16 (hi,lo) pairs.
__global__ __launch_bounds__(256)
void transpose_pairs(WPtrs4 w,
                     bf16* __restrict__ WTqh, bf16* __restrict__ WTql,
                     bf16* __restrict__ WTkh, bf16* __restrict__ WTkl)
{
    __shared__ float t[32][33];
    const int z = blockIdx.z;
    const float* src = w.p[z];
    bf16* dh = (z & 1) ? WTkh : WTqh;
    bf16* dl = (z & 1) ? WTkl : WTql;
    const size_t base = (z >> 1) ? SSZ : 0;

    const int tx = threadIdx.x, ty = threadIdx.y;   // 32 x 8
    const int x = blockIdx.x * 32 + tx;
    const int y = blockIdx.y * 32 + ty;
    #pragma unroll
    for (int r = 0; r < 4; r++)
        t[ty + r * 8][tx] = src[(size_t)(y + r * 8) * SEQ + x];
    __syncthreads();
    const int x2 = blockIdx.y * 32 + tx;
    const int y2 = blockIdx.x * 32 + ty;
    #pragma unroll
    for (int r = 0; r < 4; r++) {
        float f = t[tx][ty + r * 8];
        bf16 h = __float2bfloat16(f);
        const size_t idx = base + (size_t)(y2 + r * 8) * SEQ + x2;
        dh[idx] = h;
        dl[idx] = __float2bfloat16(f - __bfloat162float(h));
    }
}

// softmax of S row r (r in [0, 2*MROWS)); writes into Acat[h*S+s][i*2048 + :]
__global__ __launch_bounds__(256)
void softmax_cat(const float* __restrict__ S, bf16* __restrict__ Ph,
                 bf16* __restrict__ Pl)
{
    const int tid = threadIdx.x;
    const int r = blockIdx.x;
    const int branch = r >> 14;           // 0 or 1 (MROWS = 2^14)
    const int hs = r & (MROWS - 1);
    const float* p = S + (size_t)r * SEQ;
    const size_t dst = (size_t)hs * 4096 + (size_t)branch * SEQ;
    bf16* oh = Ph + dst;
    bf16* ol = Pl + dst;
    __shared__ float buf[SEQ];
    __shared__ float red[256];

    float m = -INFINITY;
    for (int i = tid; i < SEQ; i += 256) { float v = p[i]; buf[i] = v; m = fmaxf(m, v); }
    red[tid] = m; __syncthreads();
    for (int s = 128; s > 0; s >>= 1) { if (tid < s) red[tid] = fmaxf(red[tid], red[tid + s]); __syncthreads(); }
    m = red[0]; __syncthreads();

    float sum = 0.0f;
    for (int i = tid; i < SEQ; i += 256) { float e = __expf(buf[i] - m); buf[i] = e; sum += e; }
    red[tid] = sum; __syncthreads();
    for (int s = 128; s > 0; s >>= 1) { if (tid < s) red[tid] += red[tid + s]; __syncthreads(); }
    const float inv = 1.0f / red[0]; __syncthreads();

    for (int i = tid; i < SEQ; i += 256) {
        float f = buf[i] * inv;
        bf16 h = __float2bfloat16(f);
        oh[i] = h;
        ol[i] = __float2bfloat16(f - __bfloat162float(h));
    }
}

// ---------------- host side ----------------
template <typename T>
static T* sym_addr(T* symbol) {
    void* p = nullptr;
    cudaGetSymbolAddress(&p, (const void*)symbol);
    return (T*)p;
}

// Mrows multiple of 128; K multiple of 2048; lda = ldb = K.
static void run_hgemm(const bf16* Ah, const bf16* Al, int azHi, int azLo,
                      const bf16* Bh, const bf16* Bl, int bzHi, int bzLo,
                      int Mrows, int Ncols, int K, int ldc, int batch, int epi,
                      float* Cf, bf16* Ch, bf16* Cl, size_t sC, float alpha)
{
    dim3 grid(Ncols / 128, Mrows / 128, batch);
    if (epi == 0)
        hgemm3<0><<<grid, 256, SMEM_HG>>>(Ah, Al, Bh, Bl, Cf, Ch, Cl,
                                          K, ldc, sC, azHi, azLo, bzHi, bzLo, alpha);
    else if (epi == 1)
        hgemm3<1><<<grid, 256, SMEM_HG>>>(Ah, Al, Bh, Bl, Cf, Ch, Cl,
                                          K, ldc, sC, azHi, azLo, bzHi, bzLo, alpha);
    else
        hgemm3<2><<<grid, 256, SMEM_HG>>>(Ah, Al, Bh, Bl, Cf, Ch, Cl,
                                          K, ldc, sC, azHi, azLo, bzHi, bzLo, alpha);
}

extern "C" void kernel_launch(void* const* d_in, const int* in_sizes, int n_in,
                              void* d_out, int out_size)
{
    (void)in_sizes; (void)n_in; (void)out_size;
    const float* x = (const float*)d_in[0];
    WPtrs4 wqk;
    wqk.p[0] = (const float*)d_in[1];   // Wq1
    wqk.p[1] = (const float*)d_in[2];   // Wk1
    wqk.p[2] = (const float*)d_in[3];   // Wq2
    wqk.p[3] = (const float*)d_in[4];   // Wk2
    WPtrs3 wv;
    wv.p[0] = (const float*)d_in[5];    // Wv
    wv.p[1] = (const float*)d_in[6];    // W1
    wv.p[2] = (const float*)d_in[7];    // W2
    float* out = (float*)d_out;

    cudaFuncSetAttribute((const void*)hgemm3<0>,
                         cudaFuncAttributeMaxDynamicSharedMemorySize, SMEM_HG);
    cudaFuncSetAttribute((const void*)hgemm3<1>,
                         cudaFuncAttributeMaxDynamicSharedMemorySize, SMEM_HG);
    cudaFuncSetAttribute((const void*)hgemm3<2>,
                         cudaFuncAttributeMaxDynamicSharedMemorySize, SMEM_HG);

    bf16 *xh = sym_addr(g_xh),   *xl = sym_addr(g_xl);
    bf16 *Wvh = sym_addr(g_Wvh), *Wvl = sym_addr(g_Wvl);
    bf16 *Wch = sym_addr(g_Wch), *Wcl = sym_addr(g_Wcl);
    bf16 *WTqh = sym_addr(g_WTqh), *WTql = sym_addr(g_WTql);
    bf16 *WTkh = sym_addr(g_WTkh), *WTkl = sym_addr(g_WTkl);
    bf16 *Nhh = sym_addr(g_Nh),  *Nll = sym_addr(g_Nl);
    bf16 *Thh = sym_addr(g_Th),  *Tll = sym_addr(g_Tl);
    bf16 *Vth = sym_addr(g_Vth), *Vtl = sym_addr(g_Vtl);
    bf16 *Ahh = sym_addr(g_Ah),  *All = sym_addr(g_Al);
    bf16 *Chh = sym_addr(g_Ch),  *Cll = sym_addr(g_Cl);
    float *S = sym_addr(g_S);

    const float scale = 1.0f / sqrtf((float)SEQ);

    // [0] conversions: x, Wv, Wcat=[W1|-W2]
    convert_all<<<dim3(1024, 2), 256>>>(x, wv, xh, xl, Wvh, Wvl, Wch, Wcl);

    // [1] transposes: Wq1,Wk1,Wq2,Wk2 -> WTq/WTk bf16 pairs
    transpose_pairs<<<dim3(SEQ / 32, SEQ / 32, 4), dim3(32, 8)>>>(
        wqk, WTqh, WTql, WTkh, WTkl);

    // [2] N_i = WTk_i @ WTq_i^T   (z = i, 2 batches)
    run_hgemm(WTkh, WTkl, 0, SEQ, WTqh, WTql, 0, SEQ,
              SEQ, SEQ, SEQ, SEQ, 2, 1, nullptr, Nhh, Nll, SSZ, 1.0f);

    // [3] T_i = X @ N_i^T   (z = i, full M = 16384)
    run_hgemm(xh, xl, 0, 0, Nhh, Nll, 0, SEQ,
              MROWS, SEQ, SEQ, SEQ, 2, 1, nullptr, Thh, Tll, NTOT, 1.0f);

    // [4] Vt[h] = Wv @ X[h]^T   (z = head)
    run_hgemm(Wvh, Wvl, 0, 0, xh, xl, 0, SEQ,
              SEQ, SEQ, SEQ, SEQ, NH, 1, nullptr, Vth, Vtl, SSZ, 1.0f);

    // [5] logits: S[i][h] = scale * T_i[h] @ X[h]^T   (z = i*8+h, 16 batches)
    run_hgemm(Thh, Tll, MROWS, SEQ, xh, xl, 0, SEQ,
              SEQ, SEQ, SEQ, SEQ, 2 * NH, 0, S, nullptr, nullptr, SSZ, scale);

    // [6] softmax rows -> Acat bf16 pairs ([h*S+s][branch*2048 + :], ld 4096)
    softmax_cat<<<2 * MROWS, 256>>>(S, Ahh, All);

    // [7] circle[h] = (Acat[h] @ Wcat^T)^2  -- K=4096, squared epilogue
    run_hgemm(Ahh, All, 0, SEQ, Wch, Wcl, 0, 0,
              SEQ, SEQ, 2 * SEQ, SEQ, NH, 2, nullptr, Chh, Cll, SSZ, 1.0f);

    // [8] out[h] = circle[h] @ Vt[h]^T -> fp32
    run_hgemm(Chh, Cll, 0, SEQ, Vth, Vtl, 0, SEQ,
              SEQ, SEQ, SEQ, SEQ, NH, 0, out, nullptr, nullptr, SSZ, 1.0f);
}

// round 13
// speedup vs baseline: 1.0421x; 1.0017x over previous
#include <cuda_runtime.h>
#include <cuda_bf16.h>
#include <math.h>
#include <stdint.h>
#include <stddef.h>

// ============================================================================
// biSoftmax on GB300 via HMMA (mma.sync bf16) split-precision GEMMs.
// R13: fix the de-phase bit. R12 used khog=(wid>>1)&1, which puts BOTH warps
//      of each CTA on a given SMSP (wid%4) in the SAME phase -- no intra-SMSP
//      LDSM/MMA overlap ever happened. khog=wm=(wid>>2)&1 makes the two
//      same-SMSP warps opposite-phase. Everything else identical to R12.
// All GEMMs are NT: C[m,n] = alpha * sum_k A[m,k] * B[n,k]
// fp32 operands stored as bf16 (hi,lo); accumulate Ahi*Bhi + Ahi*Blo + Alo*Bhi.
// ============================================================================

#define SEQ 2048
#define NH 8
#define MROWS (NH * SEQ)                 // 16384
#define SSZ ((size_t)SEQ * SEQ)          // 2^22
#define NTOT ((size_t)MROWS * SEQ)       // 2^25

typedef __nv_bfloat16 bf16;

// ---------------- scratch (device globals, allocation-free) ----------------
__device__ bf16 g_xh[NTOT],       g_xl[NTOT];
__device__ bf16 g_Wvh[SSZ],       g_Wvl[SSZ];        // Wv
__device__ bf16 g_Wch[2 * SSZ],   g_Wcl[2 * SSZ];    // Wcat = [W1 | -W2], ld 4096
__device__ bf16 g_WTqh[2 * SSZ],  g_WTql[2 * SSZ];   // Wq1^T, Wq2^T
__device__ bf16 g_WTkh[2 * SSZ],  g_WTkl[2 * SSZ];   // Wk1^T, Wk2^T
__device__ bf16 g_Nh[2 * SSZ],    g_Nl[2 * SSZ];     // N_i = Wk_i^T Wq_i
__device__ bf16 g_Th[2 * NTOT],   g_Tl[2 * NTOT];    // T_i = X N_i^T
__device__ bf16 g_Vth[NTOT],      g_Vtl[NTOT];       // [h][e][t]
__device__ bf16 g_Ah[2 * NTOT],   g_Al[2 * NTOT];    // Acat: [h*S+s][4096]
__device__ bf16 g_Ch[NTOT],       g_Cl[NTOT];        // circle
__device__ float g_S[2 * NTOT];                      // logits (fp32)

// ---------------- PTX helpers ----------------
__device__ __forceinline__ uint32_t smem_u32(const void* p) {
    uint32_t a;
    asm("{ .reg .u64 t; cvta.to.shared.u64 t, %1; cvt.u32.u64 %0, t; }" : "=r"(a) : "l"(p));
    return a;
}

#define CP16(dst, src) \
    asm volatile("cp.async.cg.shared.global [%0], [%1], 16;" :: "r"(dst), "l"(src) : "memory")
#define CP_COMMIT() asm volatile("cp.async.commit_group;" ::: "memory")
#define CP_WAIT1()  asm volatile("cp.async.wait_group 1;" ::: "memory")

#define LDSM4(r0, r1, r2, r3, a) \
    asm volatile("ldmatrix.sync.aligned.m8n8.x4.shared.b16 {%0,%1,%2,%3}, [%4];" \
        : "=r"(r0), "=r"(r1), "=r"(r2), "=r"(r3) : "r"(a))

#define MMA_BF16(d, a, b) \
    asm volatile("mma.sync.aligned.m16n8k16.row.col.f32.bf16.bf16.f32 " \
        "{%0,%1,%2,%3}, {%4,%5,%6,%7}, {%8,%9}, {%0,%1,%2,%3};" \
        : "+f"((d)[0]), "+f"((d)[1]), "+f"((d)[2]), "+f"((d)[3]) \
        : "r"((a)[0]), "r"((a)[1]), "r"((a)[2]), "r"((a)[3]), "r"((b)[0]), "r"((b)[1]))

// ---------------- HMMA split-precision GEMM ----------------
// CTA tile 128x128, BK=32, 3 stages, 256 threads (8 warps of 64x32), 2 CTAs/SM.
// smem row = 32 bf16 = 64B packed; chunk c of row r at r*64+((c^((r>>1)&3))<<4).
// Stage: Ahi[0,8K) Alo[8K,16K) Bhi[16K,24K) Blo[24K,32K)
static constexpr int STAGE_B = 32768;
static constexpr int SMEM_HG = 3 * STAGE_B;   // 98304 -> 2 CTAs/SM (192KB)

// z decomposition: zi = z>>3, zr = z&7; row offsets = zi*Hi + zr*Lo
// EPI: 0 = fp32 * alpha, 1 = bf16 (hi,lo) pair, 2 = square -> bf16 pair
template <int EPI>
__global__ __launch_bounds__(256, 2)
void hgemm3(const bf16* __restrict__ Ah, const bf16* __restrict__ Al,
            const bf16* __restrict__ Bh, const bf16* __restrict__ Bl,
            float* __restrict__ Cf, bf16* __restrict__ Ch, bf16* __restrict__ Cl,
            int K, int ldc, size_t sC,
            int azHi, int azLo, int bzHi, int bzLo, float alpha)
{
    extern __shared__ char smem[];
    const uint32_t sbase = smem_u32(smem);
    const int tid  = threadIdx.x;
    const int lane = tid & 31;
    const int wid  = tid >> 5;
    const int wm   = wid >> 2;          // 0..1 -> 64-row slab
    const int wn   = wid & 3;           // 0..3 -> 32-col slab
    const int khog = wm;                // phase bit: differs between the two
                                        // warps sharing an SMSP (wid, wid+4)
    const int row0 = blockIdx.y * 128;
    const int col0 = blockIdx.x * 128;
    const int z    = blockIdx.z;
    const int zi   = z >> 3, zr = z & 7;
    const int aoff = zi * azHi + zr * azLo;
    const int boff = zi * bzHi + zr * bzLo;

    // ---- loader lanes: 256 threads, each 2x16B per buffer per stage ----
    const int lr  = tid >> 1;           // 0..127 row
    const int lcb = (tid & 1) * 2;      // chunk 0 or 2
    const size_t arow = (size_t)(row0 + aoff + lr);
    const size_t brow = (size_t)(col0 + boff + lr);
    const bf16* pAh = Ah + arow * K + lcb * 8;
    const bf16* pAl = Al + arow * K + lcb * 8;
    const bf16* pBh = Bh + brow * K + lcb * 8;
    const bf16* pBl = Bl + brow * K + lcb * 8;
    const uint32_t lsw = (uint32_t)((lr >> 1) & 3);
    const uint32_t st1 = lr * 64 + (((uint32_t)lcb ^ lsw) << 4);
    const uint32_t st2 = lr * 64 + ((((uint32_t)lcb + 1u) ^ lsw) << 4);

    auto prefetch = [&](int go, int stage) {
        const uint32_t sb = sbase + (uint32_t)stage * STAGE_B;
        CP16(sb +          st1, pAh + go); CP16(sb +          st2, pAh + go + 8);
        CP16(sb +  8192u + st1, pAl + go); CP16(sb +  8192u + st2, pAl + go + 8);
        CP16(sb + 16384u + st1, pBh + go); CP16(sb + 16384u + st2, pBh + go + 8);
        CP16(sb + 24576u + st1, pBl + go); CP16(sb + 24576u + st2, pBl + go + 8);
    };

    // ---- fragment addressing ----
    const int lr16  = lane & 15;
    const uint32_t khalf = (uint32_t)(lane >> 4);
    const uint32_t fsw   = (uint32_t)((lr16 >> 1) & 3);
    uint32_t a_base[4], b_base[2];
    #pragma unroll
    for (int mi = 0; mi < 4; mi++) a_base[mi] = (uint32_t)(wm * 64 + mi * 16 + lr16) * 64u;
    #pragma unroll
    for (int g = 0; g < 2; g++)    b_base[g]  = (uint32_t)(wn * 32 + g * 16 + lr16) * 64u;

    float acc[4][4][4];
    #pragma unroll
    for (int mi = 0; mi < 4; mi++)
        #pragma unroll
        for (int nj = 0; nj < 4; nj++)
            #pragma unroll
            for (int q = 0; q < 4; q++) acc[mi][nj][q] = 0.0f;

    // one 16-k slice, term-major MMA order
    auto slice = [&](uint32_t stg, int ks) {
        const uint32_t coff = ((((uint32_t)(ks * 2) + khalf) ^ fsw) << 4);
        uint32_t Bhi[4][2], Blo[4][2];
        #pragma unroll
        for (int g = 0; g < 2; g++) {
            uint32_t q0, q1, q2, q3;
            LDSM4(q0, q1, q2, q3, stg + 16384u + b_base[g] + coff);
            Bhi[2 * g][0] = q0;     Bhi[2 * g][1] = q2;
            Bhi[2 * g + 1][0] = q1; Bhi[2 * g + 1][1] = q3;
            LDSM4(q0, q1, q2, q3, stg + 24576u + b_base[g] + coff);
            Blo[2 * g][0] = q0;     Blo[2 * g][1] = q2;
            Blo[2 * g + 1][0] = q1; Blo[2 * g + 1][1] = q3;
        }
        uint32_t Ahi[4][4];
        #pragma unroll
        for (int mi = 0; mi < 4; mi++)
            LDSM4(Ahi[mi][0], Ahi[mi][1], Ahi[mi][2], Ahi[mi][3],
                  stg + a_base[mi] + coff);

        #pragma unroll
        for (int mi = 0; mi < 4; mi++)
            #pragma unroll
            for (int nj = 0; nj < 4; nj++)
                MMA_BF16(acc[mi][nj], Ahi[mi], Bhi[nj]);
        #pragma unroll
        for (int mi = 0; mi < 4; mi++)
            #pragma unroll
            for (int nj = 0; nj < 4; nj++)
                MMA_BF16(acc[mi][nj], Ahi[mi], Blo[nj]);
        #pragma unroll
        for (int mi = 0; mi < 4; mi++) {
            uint32_t Alo[4];
            LDSM4(Alo[0], Alo[1], Alo[2], Alo[3],
                  stg + 8192u + a_base[mi] + coff);
            #pragma unroll
            for (int nj = 0; nj < 4; nj++)
                MMA_BF16(acc[mi][nj], Alo, Bhi[nj]);
        }
    };

    const int nk = K >> 5;

    prefetch(0, 0);  CP_COMMIT();
    prefetch(32, 1); CP_COMMIT();

    int cs = 0;           // compute stage
    int ps = 2;           // prefetch stage
    int gof = 64;         // next global k-offset to fetch
    for (int kt = 0; kt < nk; kt++) {
        CP_WAIT1();
        __syncthreads();

        const uint32_t stg = sbase + (uint32_t)cs * STAGE_B;

        // opposite-phase halves: at any instant, each SMSP has one warp in
        // its LDSM phase and one issuing MMAs.
        slice(stg, khog);

        // prefetch between the slices (port pressure spread across the kstep)
        if (kt + 2 < nk) { prefetch(gof, ps); gof += 32; }
        CP_COMMIT();

        slice(stg, 1 - khog);

        cs = (cs == 2) ? 0 : cs + 1;
        ps = (ps == 2) ? 0 : ps + 1;
    }

    // ---- epilogue ----
    const size_t cb = (size_t)z * sC;
    #pragma unroll
    for (int mi = 0; mi < 4; mi++) {
        #pragma unroll
        for (int nj = 0; nj < 4; nj++) {
            const int rg = row0 + wm * 64 + mi * 16 + (lane >> 2);
            const int cg = col0 + wn * 32 + nj * 8 + (lane & 3) * 2;
            float d0 = acc[mi][nj][0] * alpha, d1 = acc[mi][nj][1] * alpha;
            float d2 = acc[mi][nj][2] * alpha, d3 = acc[mi][nj][3] * alpha;
            if (EPI == 2) { d0 *= d0; d1 *= d1; d2 *= d2; d3 *= d3; }
            const size_t i0 = cb + (size_t)rg * ldc + cg;
            const size_t i1 = cb + (size_t)(rg + 8) * ldc + cg;
            if (EPI == 0) {
                *(float2*)(Cf + i0) = make_float2(d0, d1);
                *(float2*)(Cf + i1) = make_float2(d2, d3);
            } else {
                __nv_bfloat162 h, l;
                h.x = __float2bfloat16(d0);
                h.y = __float2bfloat16(d1);
                l.x = __float2bfloat16(d0 - __bfloat162float(h.x));
                l.y = __float2bfloat16(d1 - __bfloat162float(h.y));
                *(__nv_bfloat162*)(Ch + i0) = h;
                *(__nv_bfloat162*)(Cl + i0) = l;
                h.x = __float2bfloat16(d2);
                h.y = __float2bfloat16(d3);
                l.x = __float2bfloat16(d2 - __bfloat162float(h.x));
                l.y = __float2bfloat16(d3 - __bfloat162float(h.y));
                *(__nv_bfloat162*)(Ch + i1) = h;
                *(__nv_bfloat162*)(Cl + i1) = l;
            }
        }
    }
}

// ---------------- conversions ----------------
struct WPtrs3 { const float* p[3]; };   // Wv, W1, W2
struct WPtrs4 { const float* p[4]; };   // Wq1, Wk1, Wq2, Wk2

// y==0: x -> pair. y==1: Wv -> pair; Wcat=[W1|-W2] (ld 4096) -> pair.
__global__ __launch_bounds__(256)
void convert_all(const float* __restrict__ x, WPtrs3 w,
                 bf16* __restrict__ xh, bf16* __restrict__ xl,
                 bf16* __restrict__ Wvh, bf16* __restrict__ Wvl,
                 bf16* __restrict__ Wch, bf16* __restrict__ Wcl)
{
    const size_t stride = (size_t)gridDim.x * blockDim.x;
    size_t i = (size_t)blockIdx.x * blockDim.x + threadIdx.x;
    if (blockIdx.y == 0) {
        for (; i < NTOT; i += stride) {
            float f = x[i];
            bf16 h = __float2bfloat16(f);
            xh[i] = h;
            xl[i] = __float2bfloat16(f - __bfloat162float(h));
        }
    } else {
        const size_t n = 3 * SSZ;
        for (; i < n; i += stride) {
            if (i < SSZ) {
                float f = w.p[0][i];
                bf16 h = __float2bfloat16(f);
                Wvh[i] = h;
                Wvl[i] = __float2bfloat16(f - __bfloat162float(h));
            } else {
                const size_t j = i - SSZ;
                const size_t u = j >> 12;          // row (4096 cols)
                const int k = (int)(j & 4095);
                float f = (k < SEQ) ? w.p[1][u * SEQ + k]
                                    : -w.p[2][u * SEQ + (k - SEQ)];
                bf16 h = __float2bfloat16(f);
                Wch[j] = h;
                Wcl[j] = __float2bfloat16(f - __bfloat162float(h));
            }
        }
    }
}

// Transpose Wq1,Wk1,Wq2,Wk2 (fp32 [SEQ,SEQ]) -> bf16 (hi,lo) pairs.
__global__ __launch_bounds__(256)
void transpose_pairs(WPtrs4 w,
                     bf16* __restrict__ WTqh, bf16* __restrict__ WTql,
                     bf16* __restrict__ WTkh, bf16* __restrict__ WTkl)
{
    __shared__ float t[32][33];
    const int z = blockIdx.z;
    const float* src = w.p[z];
    bf16* dh = (z & 1) ? WTkh : WTqh;
    bf16* dl = (z & 1) ? WTkl : WTql;
    const size_t base = (z >> 1) ? SSZ : 0;

    const int tx = threadIdx.x, ty = threadIdx.y;   // 32 x 8
    const int x = blockIdx.x * 32 + tx;
    const int y = blockIdx.y * 32 + ty;
    #pragma unroll
    for (int r = 0; r < 4; r++)
        t[ty + r * 8][tx] = src[(size_t)(y + r * 8) * SEQ + x];
    __syncthreads();
    const int x2 = blockIdx.y * 32 + tx;
    const int y2 = blockIdx.x * 32 + ty;
    #pragma unroll
    for (int r = 0; r < 4; r++) {
        float f = t[tx][ty + r * 8];
        bf16 h = __float2bfloat16(f);
        const size_t idx = base + (size_t)(y2 + r * 8) * SEQ + x2;
        dh[idx] = h;
        dl[idx] = __float2bfloat16(f - __bfloat162float(h));
    }
}

// softmax of S row r (r in [0, 2*MROWS)); writes into Acat[h*S+s][i*2048 + :]
__global__ __launch_bounds__(256)
void softmax_cat(const float* __restrict__ S, bf16* __restrict__ Ph,
                 bf16* __restrict__ Pl)
{
    const int tid = threadIdx.x;
    const int r = blockIdx.x;
    const int branch = r >> 14;           // 0 or 1 (MROWS = 2^14)
    const int hs = r & (MROWS - 1);
    const float* p = S + (size_t)r * SEQ;
    const size_t dst = (size_t)hs * 4096 + (size_t)branch * SEQ;
    bf16* oh = Ph + dst;
    bf16* ol = Pl + dst;
    __shared__ float buf[SEQ];
    __shared__ float red[256];

    float m = -INFINITY;
    for (int i = tid; i < SEQ; i += 256) { float v = p[i]; buf[i] = v; m = fmaxf(m, v); }
    red[tid] = m; __syncthreads();
    for (int s = 128; s > 0; s >>= 1) { if (tid < s) red[tid] = fmaxf(red[tid], red[tid + s]); __syncthreads(); }
    m = red[0]; __syncthreads();

    float sum = 0.0f;
    for (int i = tid; i < SEQ; i += 256) { float e = __expf(buf[i] - m); buf[i] = e; sum += e; }
    red[tid] = sum; __syncthreads();
    for (int s = 128; s > 0; s >>= 1) { if (tid < s) red[tid] += red[tid + s]; __syncthreads(); }
    const float inv = 1.0f / red[0]; __syncthreads();

    for (int i = tid; i < SEQ; i += 256) {
        float f = buf[i] * inv;
        bf16 h = __float2bfloat16(f);
        oh[i] = h;
        ol[i] = __float2bfloat16(f - __bfloat162float(h));
    }
}

// ---------------- host side ----------------
template <typename T>
static T* sym_addr(T* symbol) {
    void* p = nullptr;
    cudaGetSymbolAddress(&p, (const void*)symbol);
    return (T*)p;
}

// Mrows multiple of 128; K multiple of 2048; lda = ldb = K.
static void run_hgemm(const bf16* Ah, const bf16* Al, int azHi, int azLo,
                      const bf16* Bh, const bf16* Bl, int bzHi, int bzLo,
                      int Mrows, int Ncols, int K, int ldc, int batch, int epi,
                      float* Cf, bf16* Ch, bf16* Cl, size_t sC, float alpha)
{
    dim3 grid(Ncols / 128, Mrows / 128, batch);
    if (epi == 0)
        hgemm3<0><<<grid, 256, SMEM_HG>>>(Ah, Al, Bh, Bl, Cf, Ch, Cl,
                                          K, ldc, sC, azHi, azLo, bzHi, bzLo, alpha);
    else if (epi == 1)
        hgemm3<1><<<grid, 256, SMEM_HG>>>(Ah, Al, Bh, Bl, Cf, Ch, Cl,
                                          K, ldc, sC, azHi, azLo, bzHi, bzLo, alpha);
    else
        hgemm3<2><<<grid, 256, SMEM_HG>>>(Ah, Al, Bh, Bl, Cf, Ch, Cl,
                                          K, ldc, sC, azHi, azLo, bzHi, bzLo, alpha);
}

extern "C" void kernel_launch(void* const* d_in, const int* in_sizes, int n_in,
                              void* d_out, int out_size)
{
    (void)in_sizes; (void)n_in; (void)out_size;
    const float* x = (const float*)d_in[0];
    WPtrs4 wqk;
    wqk.p[0] = (const float*)d_in[1];   // Wq1
    wqk.p[1] = (const float*)d_in[2];   // Wk1
    wqk.p[2] = (const float*)d_in[3];   // Wq2
    wqk.p[3] = (const float*)d_in[4];   // Wk2
    WPtrs3 wv;
    wv.p[0] = (const float*)d_in[5];    // Wv
    wv.p[1] = (const float*)d_in[6];    // W1
    wv.p[2] = (const float*)d_in[7];    // W2
    float* out = (float*)d_out;

    cudaFuncSetAttribute((const void*)hgemm3<0>,
                         cudaFuncAttributeMaxDynamicSharedMemorySize, SMEM_HG);
    cudaFuncSetAttribute((const void*)hgemm3<1>,
                         cudaFuncAttributeMaxDynamicSharedMemorySize, SMEM_HG);
    cudaFuncSetAttribute((const void*)hgemm3<2>,
                         cudaFuncAttributeMaxDynamicSharedMemorySize, SMEM_HG);

    bf16 *xh = sym_addr(g_xh),   *xl = sym_addr(g_xl);
    bf16 *Wvh = sym_addr(g_Wvh), *Wvl = sym_addr(g_Wvl);
    bf16 *Wch = sym_addr(g_Wch), *Wcl = sym_addr(g_Wcl);
    bf16 *WTqh = sym_addr(g_WTqh), *WTql = sym_addr(g_WTql);
    bf16 *WTkh = sym_addr(g_WTkh), *WTkl = sym_addr(g_WTkl);
    bf16 *Nhh = sym_addr(g_Nh),  *Nll = sym_addr(g_Nl);
    bf16 *Thh = sym_addr(g_Th),  *Tll = sym_addr(g_Tl);
    bf16 *Vth = sym_addr(g_Vth), *Vtl = sym_addr(g_Vtl);
    bf16 *Ahh = sym_addr(g_Ah),  *All = sym_addr(g_Al);
    bf16 *Chh = sym_addr(g_Ch),  *Cll = sym_addr(g_Cl);
    float *S = sym_addr(g_S);

    const float scale = 1.0f / sqrtf((float)SEQ);

    // [0] conversions: x, Wv, Wcat=[W1|-W2]
    convert_all<<<dim3(1024, 2), 256>>>(x, wv, xh, xl, Wvh, Wvl, Wch, Wcl);

    // [1] transposes: Wq1,Wk1,Wq2,Wk2 -> WTq/WTk bf16 pairs
    transpose_pairs<<<dim3(SEQ / 32, SEQ / 32, 4), dim3(32, 8)>>>(
        wqk, WTqh, WTql, WTkh, WTkl);

    // [2] N_i = WTk_i @ WTq_i^T   (z = i, 2 batches)
    run_hgemm(WTkh, WTkl, 0, SEQ, WTqh, WTql, 0, SEQ,
              SEQ, SEQ, SEQ, SEQ, 2, 1, nullptr, Nhh, Nll, SSZ, 1.0f);

    // [3] T_i = X @ N_i^T   (z = i, full M = 16384)
    run_hgemm(xh, xl, 0, 0, Nhh, Nll, 0, SEQ,
              MROWS, SEQ, SEQ, SEQ, 2, 1, nullptr, Thh, Tll, NTOT, 1.0f);

    // [4] Vt[h] = Wv @ X[h]^T   (z = head)
    run_hgemm(Wvh, Wvl, 0, 0, xh, xl, 0, SEQ,
              SEQ, SEQ, SEQ, SEQ, NH, 1, nullptr, Vth, Vtl, SSZ, 1.0f);

    // [5] logits: S[i][h] = scale * T_i[h] @ X[h]^T   (z = i*8+h, 16 batches)
    run_hgemm(Thh, Tll, MROWS, SEQ, xh, xl, 0, SEQ,
              SEQ, SEQ, SEQ, SEQ, 2 * NH, 0, S, nullptr, nullptr, SSZ, scale);

    // [6] softmax rows -> Acat bf16 pairs ([h*S+s][branch*2048 + :], ld 4096)
    softmax_cat<<<2 * MROWS, 256>>>(S, Ahh, All);

    // [7] circle[h] = (Acat[h] @ Wcat^T)^2  -- K=4096, squared epilogue
    run_hgemm(Ahh, All, 0, SEQ, Wch, Wcl, 0, 0,
              SEQ, SEQ, 2 * SEQ, SEQ, NH, 2, nullptr, Chh, Cll, SSZ, 1.0f);

    // [8] out[h] = circle[h] @ Vt[h]^T -> fp32
    run_hgemm(Chh, Cll, 0, SEQ, Vth, Vtl, 0, SEQ,
              SEQ, SEQ, SEQ, SEQ, NH, 0, out, nullptr, nullptr, SSZ, 1.0f);
}

// round 14
// speedup vs baseline: 1.1970x; 1.1486x over previous
#include <cuda_runtime.h>
#include <cuda_bf16.h>
#include <cuda_fp16.h>
#include <math.h>
#include <stdint.h>
#include <stddef.h>

// ============================================================================
// biSoftmax on GB300 via HMMA (mma.sync) split-precision GEMMs.
// R14: precision-budget reallocation. Early chain (N, T, Vt, logits) stays
//      bf16 3-product (error ~8e-5). The tail (circle K=4096, out) switches to
//      fp16 2-product (Ahi*Bhi + Ahi*Blo): Acat stored fp16 hi-only, circle
//      stored fp16 hi-only scaled x4096 (keeps values in fp16-normal range),
//      Wcat/Vt stored fp16 (hi,lo). Issued tensor work 198 -> 174 product-
//      units (-12%); softmax write traffic halved; Alo fills skipped in the
//      2-product GEMMs.
// All GEMMs are NT: C[m,n] = alpha * sum_k A[m,k] * B[n,k]
// ============================================================================

#define SEQ 2048
#define NH 8
#define MROWS (NH * SEQ)                 // 16384
#define SSZ ((size_t)SEQ * SEQ)          // 2^22
#define NTOT ((size_t)MROWS * SEQ)       // 2^25

typedef __nv_bfloat16 bf16;
typedef __half fp16;

// ---------------- scratch (device globals, allocation-free) ----------------
__device__ bf16 g_xh[NTOT],       g_xl[NTOT];
__device__ bf16 g_Wvh[SSZ],       g_Wvl[SSZ];        // Wv (bf16 pair)
__device__ fp16 g_Wch[2 * SSZ],   g_Wcl[2 * SSZ];    // Wcat=[W1|-W2] fp16 pair
__device__ bf16 g_WTqh[2 * SSZ],  g_WTql[2 * SSZ];   // Wq1^T, Wq2^T
__device__ bf16 g_WTkh[2 * SSZ],  g_WTkl[2 * SSZ];   // Wk1^T, Wk2^T
__device__ bf16 g_Nh[2 * SSZ],    g_Nl[2 * SSZ];     // N_i = Wk_i^T Wq_i
__device__ bf16 g_Th[2 * NTOT],   g_Tl[2 * NTOT];    // T_i = X N_i^T
__device__ fp16 g_Vth[NTOT],      g_Vtl[NTOT];       // Vt fp16 pair [h][e][t]
__device__ fp16 g_Acat[2 * NTOT];                    // softmax, fp16 hi only
__device__ fp16 g_C[NTOT];                           // circle*4096, fp16 hi only
__device__ float g_S[2 * NTOT];                      // logits (fp32)

// ---------------- PTX helpers ----------------
__device__ __forceinline__ uint32_t smem_u32(const void* p) {
    uint32_t a;
    asm("{ .reg .u64 t; cvta.to.shared.u64 t, %1; cvt.u32.u64 %0, t; }" : "=r"(a) : "l"(p));
    return a;
}

#define CP16(dst, src) \
    asm volatile("cp.async.cg.shared.global [%0], [%1], 16;" :: "r"(dst), "l"(src) : "memory")
#define CP_COMMIT() asm volatile("cp.async.commit_group;" ::: "memory")
#define CP_WAIT1()  asm volatile("cp.async.wait_group 1;" ::: "memory")

#define LDSM4(r0, r1, r2, r3, a) \
    asm volatile("ldmatrix.sync.aligned.m8n8.x4.shared.b16 {%0,%1,%2,%3}, [%4];" \
        : "=r"(r0), "=r"(r1), "=r"(r2), "=r"(r3) : "r"(a))

template <bool F16>
__device__ __forceinline__ void mma16(float* d, const uint32_t* a, const uint32_t* b) {
    if constexpr (F16) {
        asm volatile("mma.sync.aligned.m16n8k16.row.col.f32.f16.f16.f32 "
            "{%0,%1,%2,%3}, {%4,%5,%6,%7}, {%8,%9}, {%0,%1,%2,%3};"
            : "+f"(d[0]), "+f"(d[1]), "+f"(d[2]), "+f"(d[3])
            : "r"(a[0]), "r"(a[1]), "r"(a[2]), "r"(a[3]), "r"(b[0]), "r"(b[1]));
    } else {
        asm volatile("mma.sync.aligned.m16n8k16.row.col.f32.bf16.bf16.f32 "
            "{%0,%1,%2,%3}, {%4,%5,%6,%7}, {%8,%9}, {%0,%1,%2,%3};"
            : "+f"(d[0]), "+f"(d[1]), "+f"(d[2]), "+f"(d[3])
            : "r"(a[0]), "r"(a[1]), "r"(a[2]), "r"(a[3]), "r"(b[0]), "r"(b[1]));
    }
}

// ---------------- HMMA split-precision GEMM ----------------
// CTA tile 128x128, BK=32, 3 stages, 256 threads (8 warps of 64x32), 2 CTAs/SM.
// smem row = 32 x16 = 64B packed; chunk c of row r at r*64+((c^((r>>1)&3))<<4).
// Stage: Ahi[0,8K) Alo[8K,16K) Bhi[16K,24K) Blo[24K,32K)
static constexpr int STAGE_B = 32768;
static constexpr int SMEM_HG = 3 * STAGE_B;   // 98304 -> 2 CTAs/SM (192KB)

// z decomposition: zi = z>>3, zr = z&7; row offsets = zi*Hi + zr*Lo
// EPI: 0 = fp32*alpha, 1 = bf16 (hi,lo), 2 = fp16 hi of (d*alpha)^2, 3 = fp16 (hi,lo)
// F16M: operand type for MMA. NPROD: 3 = full split, 2 = Ahi*(Bhi+Blo).
template <int EPI, bool F16M, int NPROD>
__global__ __launch_bounds__(256, 2)
void hgemm3(const uint16_t* __restrict__ Ah, const uint16_t* __restrict__ Al,
            const uint16_t* __restrict__ Bh, const uint16_t* __restrict__ Bl,
            float* __restrict__ Cf, void* __restrict__ Cho, void* __restrict__ Clo,
            int K, int ldc, size_t sC,
            int azHi, int azLo, int bzHi, int bzLo, float alpha)
{
    extern __shared__ char smem[];
    const uint32_t sbase = smem_u32(smem);
    const int tid  = threadIdx.x;
    const int lane = tid & 31;
    const int wid  = tid >> 5;
    const int wm   = wid >> 2;
    const int wn   = wid & 3;
    const int khog = wm;                // de-phase bit (kept from R12/13)
    const int row0 = blockIdx.y * 128;
    const int col0 = blockIdx.x * 128;
    const int z    = blockIdx.z;
    const int zi   = z >> 3, zr = z & 7;
    const int aoff = zi * azHi + zr * azLo;
    const int boff = zi * bzHi + zr * bzLo;

    // ---- loader lanes ----
    const int lr  = tid >> 1;
    const int lcb = (tid & 1) * 2;
    const size_t arow = (size_t)(row0 + aoff + lr);
    const size_t brow = (size_t)(col0 + boff + lr);
    const uint16_t* pAh = Ah + arow * K + lcb * 8;
    const uint16_t* pAl = (NPROD == 3) ? (Al + arow * K + lcb * 8) : pAh;
    const uint16_t* pBh = Bh + brow * K + lcb * 8;
    const uint16_t* pBl = Bl + brow * K + lcb * 8;
    const uint32_t lsw = (uint32_t)((lr >> 1) & 3);
    const uint32_t st1 = lr * 64 + (((uint32_t)lcb ^ lsw) << 4);
    const uint32_t st2 = lr * 64 + ((((uint32_t)lcb + 1u) ^ lsw) << 4);

    auto prefetch = [&](int go, int stage) {
        const uint32_t sb = sbase + (uint32_t)stage * STAGE_B;
        CP16(sb +          st1, pAh + go); CP16(sb +          st2, pAh + go + 8);
        if (NPROD == 3) {
            CP16(sb + 8192u + st1, pAl + go); CP16(sb + 8192u + st2, pAl + go + 8);
        }
        CP16(sb + 16384u + st1, pBh + go); CP16(sb + 16384u + st2, pBh + go + 8);
        CP16(sb + 24576u + st1, pBl + go); CP16(sb + 24576u + st2, pBl + go + 8);
    };

    // ---- fragment addressing ----
    const int lr16  = lane & 15;
    const uint32_t khalf = (uint32_t)(lane >> 4);
    const uint32_t fsw   = (uint32_t)((lr16 >> 1) & 3);
    uint32_t a_base[4], b_base[2];
    #pragma unroll
    for (int mi = 0; mi < 4; mi++) a_base[mi] = (uint32_t)(wm * 64 + mi * 16 + lr16) * 64u;
    #pragma unroll
    for (int g = 0; g < 2; g++)    b_base[g]  = (uint32_t)(wn * 32 + g * 16 + lr16) * 64u;

    float acc[4][4][4];
    #pragma unroll
    for (int mi = 0; mi < 4; mi++)
        #pragma unroll
        for (int nj = 0; nj < 4; nj++)
            #pragma unroll
            for (int q = 0; q < 4; q++) acc[mi][nj][q] = 0.0f;

    // one 16-k slice, term-major MMA order
    auto slice = [&](uint32_t stg, int ks) {
        const uint32_t coff = ((((uint32_t)(ks * 2) + khalf) ^ fsw) << 4);
        uint32_t Bhi[4][2], Blo[4][2];
        #pragma unroll
        for (int g = 0; g < 2; g++) {
            uint32_t q0, q1, q2, q3;
            LDSM4(q0, q1, q2, q3, stg + 16384u + b_base[g] + coff);
            Bhi[2 * g][0] = q0;     Bhi[2 * g][1] = q2;
            Bhi[2 * g + 1][0] = q1; Bhi[2 * g + 1][1] = q3;
            LDSM4(q0, q1, q2, q3, stg + 24576u + b_base[g] + coff);
            Blo[2 * g][0] = q0;     Blo[2 * g][1] = q2;
            Blo[2 * g + 1][0] = q1; Blo[2 * g + 1][1] = q3;
        }
        uint32_t Ahi[4][4];
        #pragma unroll
        for (int mi = 0; mi < 4; mi++)
            LDSM4(Ahi[mi][0], Ahi[mi][1], Ahi[mi][2], Ahi[mi][3],
                  stg + a_base[mi] + coff);

        #pragma unroll
        for (int mi = 0; mi < 4; mi++)
            #pragma unroll
            for (int nj = 0; nj < 4; nj++)
                mma16<F16M>(acc[mi][nj], Ahi[mi], Bhi[nj]);
        #pragma unroll
        for (int mi = 0; mi < 4; mi++)
            #pragma unroll
            for (int nj = 0; nj < 4; nj++)
                mma16<F16M>(acc[mi][nj], Ahi[mi], Blo[nj]);
        if (NPROD == 3) {
            #pragma unroll
            for (int mi = 0; mi < 4; mi++) {
                uint32_t Alo[4];
                LDSM4(Alo[0], Alo[1], Alo[2], Alo[3],
                      stg + 8192u + a_base[mi] + coff);
                #pragma unroll
                for (int nj = 0; nj < 4; nj++)
                    mma16<F16M>(acc[mi][nj], Alo, Bhi[nj]);
            }
        }
    };

    const int nk = K >> 5;

    prefetch(0, 0);  CP_COMMIT();
    prefetch(32, 1); CP_COMMIT();

    int cs = 0, ps = 2, gof = 64;
    for (int kt = 0; kt < nk; kt++) {
        CP_WAIT1();
        __syncthreads();

        const uint32_t stg = sbase + (uint32_t)cs * STAGE_B;
        slice(stg, khog);
        if (kt + 2 < nk) { prefetch(gof, ps); gof += 32; }
        CP_COMMIT();
        slice(stg, 1 - khog);

        cs = (cs == 2) ? 0 : cs + 1;
        ps = (ps == 2) ? 0 : ps + 1;
    }

    // ---- epilogue ----
    const size_t cb = (size_t)z * sC;
    #pragma unroll
    for (int mi = 0; mi < 4; mi++) {
        #pragma unroll
        for (int nj = 0; nj < 4; nj++) {
            const int rg = row0 + wm * 64 + mi * 16 + (lane >> 2);
            const int cg = col0 + wn * 32 + nj * 8 + (lane & 3) * 2;
            float d0 = acc[mi][nj][0] * alpha, d1 = acc[mi][nj][1] * alpha;
            float d2 = acc[mi][nj][2] * alpha, d3 = acc[mi][nj][3] * alpha;
            const size_t i0 = cb + (size_t)rg * ldc + cg;
            const size_t i1 = cb + (size_t)(rg + 8) * ldc + cg;
            if (EPI == 0) {
                *(float2*)(Cf + i0) = make_float2(d0, d1);
                *(float2*)(Cf + i1) = make_float2(d2, d3);
            } else if (EPI == 1) {
                bf16* Ch = (bf16*)Cho; bf16* Cl = (bf16*)Clo;
                __nv_bfloat162 h, l;
                h.x = __float2bfloat16(d0); h.y = __float2bfloat16(d1);
                l.x = __float2bfloat16(d0 - __bfloat162float(h.x));
                l.y = __float2bfloat16(d1 - __bfloat162float(h.y));
                *(__nv_bfloat162*)(Ch + i0) = h; *(__nv_bfloat162*)(Cl + i0) = l;
                h.x = __float2bfloat16(d2); h.y = __float2bfloat16(d3);
                l.x = __float2bfloat16(d2 - __bfloat162float(h.x));
                l.y = __float2bfloat16(d3 - __bfloat162float(h.y));
                *(__nv_bfloat162*)(Ch + i1) = h; *(__nv_bfloat162*)(Cl + i1) = l;
            } else if (EPI == 2) {
                fp16* Ch = (fp16*)Cho;
                __half2 h;
                h.x = __float2half_rn(d0 * d0); h.y = __float2half_rn(d1 * d1);
                *(__half2*)(Ch + i0) = h;
                h.x = __float2half_rn(d2 * d2); h.y = __float2half_rn(d3 * d3);
                *(__half2*)(Ch + i1) = h;
            } else {  // EPI == 3: fp16 (hi, lo)
                fp16* Ch = (fp16*)Cho; fp16* Cl = (fp16*)Clo;
                __half2 h, l;
                h.x = __float2half_rn(d0); h.y = __float2half_rn(d1);
                l.x = __float2half_rn(d0 - __half2float(h.x));
                l.y = __float2half_rn(d1 - __half2float(h.y));
                *(__half2*)(Ch + i0) = h; *(__half2*)(Cl + i0) = l;
                h.x = __float2half_rn(d2); h.y = __float2half_rn(d3);
                l.x = __float2half_rn(d2 - __half2float(h.x));
                l.y = __float2half_rn(d3 - __half2float(h.y));
                *(__half2*)(Ch + i1) = h; *(__half2*)(Cl + i1) = l;
            }
        }
    }
}

// ---------------- conversions ----------------
struct WPtrs3 { const float* p[3]; };   // Wv, W1, W2
struct WPtrs4 { const float* p[4]; };   // Wq1, Wk1, Wq2, Wk2

// y==0: x -> bf16 pair. y==1: Wv -> bf16 pair; Wcat=[W1|-W2] (ld 4096) -> fp16 pair.
__global__ __launch_bounds__(256)
void convert_all(const float* __restrict__ x, WPtrs3 w,
                 bf16* __restrict__ xh, bf16* __restrict__ xl,
                 bf16* __restrict__ Wvh, bf16* __restrict__ Wvl,
                 fp16* __restrict__ Wch, fp16* __restrict__ Wcl)
{
    const size_t stride = (size_t)gridDim.x * blockDim.x;
    size_t i = (size_t)blockIdx.x * blockDim.x + threadIdx.x;
    if (blockIdx.y == 0) {
        for (; i < NTOT; i += stride) {
            float f = x[i];
            bf16 h = __float2bfloat16(f);
            xh[i] = h;
            xl[i] = __float2bfloat16(f - __bfloat162float(h));
        }
    } else {
        const size_t n = 3 * SSZ;
        for (; i < n; i += stride) {
            if (i < SSZ) {
                float f = w.p[0][i];
                bf16 h = __float2bfloat16(f);
                Wvh[i] = h;
                Wvl[i] = __float2bfloat16(f - __bfloat162float(h));
            } else {
                const size_t j = i - SSZ;
                const size_t u = j >> 12;          // row (4096 cols)
                const int k = (int)(j & 4095);
                float f = (k < SEQ) ? w.p[1][u * SEQ + k]
                                    : -w.p[2][u * SEQ + (k - SEQ)];
                fp16 h = __float2half_rn(f);
                Wch[j] = h;
                Wcl[j] = __float2half_rn(f - __half2float(h));
            }
        }
    }
}

// Transpose Wq1,Wk1,Wq2,Wk2 (fp32 [SEQ,SEQ]) -> bf16 (hi,lo) pairs.
__global__ __launch_bounds__(256)
void transpose_pairs(WPtrs4 w,
                     bf16* __restrict__ WTqh, bf16* __restrict__ WTql,
                     bf16* __restrict__ WTkh, bf16* __restrict__ WTkl)
{
    __shared__ float t[32][33];
    const int z = blockIdx.z;
    const float* src = w.p[z];
    bf16* dh = (z & 1) ? WTkh : WTqh;
    bf16* dl = (z & 1) ? WTkl : WTql;
    const size_t base = (z >> 1) ? SSZ : 0;

    const int tx = threadIdx.x, ty = threadIdx.y;   // 32 x 8
    const int x = blockIdx.x * 32 + tx;
    const int y = blockIdx.y * 32 + ty;
    #pragma unroll
    for (int r = 0; r < 4; r++)
        t[ty + r * 8][tx] = src[(size_t)(y + r * 8) * SEQ + x];
    __syncthreads();
    const int x2 = blockIdx.y * 32 + tx;
    const int y2 = blockIdx.x * 32 + ty;
    #pragma unroll
    for (int r = 0; r < 4; r++) {
        float f = t[tx][ty + r * 8];
        bf16 h = __float2bfloat16(f);
        const size_t idx = base + (size_t)(y2 + r * 8) * SEQ + x2;
        dh[idx] = h;
        dl[idx] = __float2bfloat16(f - __bfloat162float(h));
    }
}

// softmax of S row r; writes fp16 HI ONLY into Acat[h*S+s][branch*2048 + :]
__global__ __launch_bounds__(256)
void softmax_cat(const float* __restrict__ S, fp16* __restrict__ P)
{
    const int tid = threadIdx.x;
    const int r = blockIdx.x;
    const int branch = r >> 14;           // MROWS = 2^14
    const int hs = r & (MROWS - 1);
    const float* p = S + (size_t)r * SEQ;
    fp16* oh = P + (size_t)hs * 4096 + (size_t)branch * SEQ;
    __shared__ float buf[SEQ];
    __shared__ float red[256];

    float m = -INFINITY;
    for (int i = tid; i < SEQ; i += 256) { float v = p[i]; buf[i] = v; m = fmaxf(m, v); }
    red[tid] = m; __syncthreads();
    for (int s = 128; s > 0; s >>= 1) { if (tid < s) red[tid] = fmaxf(red[tid], red[tid + s]); __syncthreads(); }
    m = red[0]; __syncthreads();

    float sum = 0.0f;
    for (int i = tid; i < SEQ; i += 256) { float e = __expf(buf[i] - m); buf[i] = e; sum += e; }
    red[tid] = sum; __syncthreads();
    for (int s = 128; s > 0; s >>= 1) { if (tid < s) red[tid] += red[tid + s]; __syncthreads(); }
    const float inv = 1.0f / red[0]; __syncthreads();

    for (int i = tid; i < SEQ; i += 256)
        oh[i] = __float2half_rn(buf[i] * inv);
}

// ---------------- host side ----------------
template <typename T>
static T* sym_addr(T* symbol) {
    void* p = nullptr;
    cudaGetSymbolAddress(&p, (const void*)symbol);
    return (T*)p;
}

template <int EPI, bool F16M, int NPROD>
static void launch_g(const void* Ah, const void* Al, int azHi, int azLo,
                     const void* Bh, const void* Bl, int bzHi, int bzLo,
                     int Mrows, int Ncols, int K, int ldc, int batch,
                     float* Cf, void* Cho, void* Clo, size_t sC, float alpha)
{
    cudaFuncSetAttribute((const void*)hgemm3<EPI, F16M, NPROD>,
                         cudaFuncAttributeMaxDynamicSharedMemorySize, SMEM_HG);
    dim3 grid(Ncols / 128, Mrows / 128, batch);
    hgemm3<EPI, F16M, NPROD><<<grid, 256, SMEM_HG>>>(
        (const uint16_t*)Ah, (const uint16_t*)Al,
        (const uint16_t*)Bh, (const uint16_t*)Bl,
        Cf, Cho, Clo, K, ldc, sC, azHi, azLo, bzHi, bzLo, alpha);
}

extern "C" void kernel_launch(void* const* d_in, const int* in_sizes, int n_in,
                              void* d_out, int out_size)
{
    (void)in_sizes; (void)n_in; (void)out_size;
    const float* x = (const float*)d_in[0];
    WPtrs4 wqk;
    wqk.p[0] = (const float*)d_in[1];   // Wq1
    wqk.p[1] = (const float*)d_in[2];   // Wk1
    wqk.p[2] = (const float*)d_in[3];   // Wq2
    wqk.p[3] = (const float*)d_in[4];   // Wk2
    WPtrs3 wv;
    wv.p[0] = (const float*)d_in[5];    // Wv
    wv.p[1] = (const float*)d_in[6];    // W1
    wv.p[2] = (const float*)d_in[7];    // W2
    float* out = (float*)d_out;

    bf16 *xh = sym_addr(g_xh),   *xl = sym_addr(g_xl);
    bf16 *Wvh = sym_addr(g_Wvh), *Wvl = sym_addr(g_Wvl);
    fp16 *Wch = sym_addr(g_Wch), *Wcl = sym_addr(g_Wcl);
    bf16 *WTqh = sym_addr(g_WTqh), *WTql = sym_addr(g_WTql);
    bf16 *WTkh = sym_addr(g_WTkh), *WTkl = sym_addr(g_WTkl);
    bf16 *Nhh = sym_addr(g_Nh),  *Nll = sym_addr(g_Nl);
    bf16 *Thh = sym_addr(g_Th),  *Tll = sym_addr(g_Tl);
    fp16 *Vth = sym_addr(g_Vth), *Vtl = sym_addr(g_Vtl);
    fp16 *Acat = sym_addr(g_Acat);
    fp16 *Cc = sym_addr(g_C);
    float *S = sym_addr(g_S);

    const float scale = 1.0f / sqrtf((float)SEQ);

    // [0] conversions: x (bf16 pair), Wv (bf16 pair), Wcat=[W1|-W2] (fp16 pair)
    convert_all<<<dim3(1024, 2), 256>>>(x, wv, xh, xl, Wvh, Wvl, Wch, Wcl);

    // [1] transposes: Wq1,Wk1,Wq2,Wk2 -> WTq/WTk bf16 pairs
    transpose_pairs<<<dim3(SEQ / 32, SEQ / 32, 4), dim3(32, 8)>>>(
        wqk, WTqh, WTql, WTkh, WTkl);

    // [2] N_i = WTk_i @ WTq_i^T  (bf16 3-prod -> bf16 pair)
    launch_g<1, false, 3>(WTkh, WTkl, 0, SEQ, WTqh, WTql, 0, SEQ,
                          SEQ, SEQ, SEQ, SEQ, 2,
                          nullptr, Nhh, Nll, SSZ, 1.0f);

    // [3] T_i = X @ N_i^T  (bf16 3-prod -> bf16 pair)
    launch_g<1, false, 3>(xh, xl, 0, 0, Nhh, Nll, 0, SEQ,
                          MROWS, SEQ, SEQ, SEQ, 2,
                          nullptr, Thh, Tll, NTOT, 1.0f);

    // [4] Vt[h] = Wv @ X[h]^T  (bf16 3-prod -> fp16 pair)
    launch_g<3, false, 3>(Wvh, Wvl, 0, 0, xh, xl, 0, SEQ,
                          SEQ, SEQ, SEQ, SEQ, NH,
                          nullptr, Vth, Vtl, SSZ, 1.0f);

    // [5] logits: S[i][h] = scale * T_i[h] @ X[h]^T  (bf16 3-prod -> fp32)
    launch_g<0, false, 3>(Thh, Tll, MROWS, SEQ, xh, xl, 0, SEQ,
                          SEQ, SEQ, SEQ, SEQ, 2 * NH,
                          S, nullptr, nullptr, SSZ, scale);

    // [6] softmax rows -> Acat fp16 hi-only ([h*S+s][branch*2048+:], ld 4096)
    softmax_cat<<<2 * MROWS, 256>>>(S, Acat);

    // [7] circle[h]*4096 = (64 * Acat[h] @ Wcat^T)^2  (fp16 2-prod, K=4096)
    launch_g<2, true, 2>(Acat, Acat, 0, SEQ, Wch, Wcl, 0, 0,
                         SEQ, SEQ, 2 * SEQ, SEQ, NH,
                         nullptr, Cc, nullptr, SSZ, 64.0f);

    // [8] out[h] = (1/4096) * circle4096[h] @ Vt[h]^T  (fp16 2-prod -> fp32)
    launch_g<0, true, 2>(Cc, Cc, 0, SEQ, Vth, Vtl, 0, SEQ,
                         SEQ, SEQ, SEQ, SEQ, NH,
                         out, nullptr, nullptr, SSZ, 1.0f / 4096.0f);
}

// round 15
// speedup vs baseline: 1.3841x; 1.1563x over previous
#include <cuda_runtime.h>
#include <cuda_bf16.h>
#include <cuda_fp16.h>
#include <math.h>
#include <stdint.h>
#include <stddef.h>

// ============================================================================
// biSoftmax on GB300 via HMMA (mma.sync fp16) split-precision GEMMs.
// R15: all-fp16 pipeline (fp16 hi = 11-bit mantissa vs bf16's 8). 2-product
//      (Ahi*Bhi + Ahi*Blo) on T, Vt, circle, out; 3-product on N and logits
//      (the softmax input stays high-precision). Issued tensor work
//      174 -> 150 product-units (-14%). Mainloop untouched (58% ceiling).
// All GEMMs are NT: C[m,n] = alpha * sum_k A[m,k] * B[n,k]
// ============================================================================

#define SEQ 2048
#define NH 8
#define MROWS (NH * SEQ)                 // 16384
#define SSZ ((size_t)SEQ * SEQ)          // 2^22
#define NTOT ((size_t)MROWS * SEQ)       // 2^25

typedef __half fp16;

// ---------------- scratch (device globals, allocation-free) ----------------
__device__ fp16 g_xh[NTOT],       g_xl[NTOT];        // x fp16 pair
__device__ fp16 g_Wvh[SSZ];                          // Wv fp16 hi (A of 2-prod)
__device__ fp16 g_Wch[2 * SSZ],   g_Wcl[2 * SSZ];    // Wcat=[W1|-W2] fp16 pair
__device__ fp16 g_WTqh[2 * SSZ],  g_WTql[2 * SSZ];   // Wq1^T, Wq2^T fp16 pair
__device__ fp16 g_WTkh[2 * SSZ],  g_WTkl[2 * SSZ];   // Wk1^T, Wk2^T fp16 pair
__device__ fp16 g_Nh[2 * SSZ],    g_Nl[2 * SSZ];     // N_i fp16 pair
__device__ fp16 g_Th[2 * NTOT],   g_Tl[2 * NTOT];    // T_i fp16 pair
__device__ fp16 g_Vth[NTOT],      g_Vtl[NTOT];       // Vt fp16 pair [h][e][t]
__device__ fp16 g_Acat[2 * NTOT];                    // softmax, fp16 hi only
__device__ fp16 g_C[NTOT];                           // circle*4096, fp16 hi
__device__ float g_S[2 * NTOT];                      // logits (fp32)

// ---------------- PTX helpers ----------------
__device__ __forceinline__ uint32_t smem_u32(const void* p) {
    uint32_t a;
    asm("{ .reg .u64 t; cvta.to.shared.u64 t, %1; cvt.u32.u64 %0, t; }" : "=r"(a) : "l"(p));
    return a;
}

#define CP16(dst, src) \
    asm volatile("cp.async.cg.shared.global [%0], [%1], 16;" :: "r"(dst), "l"(src) : "memory")
#define CP_COMMIT() asm volatile("cp.async.commit_group;" ::: "memory")
#define CP_WAIT1()  asm volatile("cp.async.wait_group 1;" ::: "memory")

#define LDSM4(r0, r1, r2, r3, a) \
    asm volatile("ldmatrix.sync.aligned.m8n8.x4.shared.b16 {%0,%1,%2,%3}, [%4];" \
        : "=r"(r0), "=r"(r1), "=r"(r2), "=r"(r3) : "r"(a))

__device__ __forceinline__ void mmaf16(float* d, const uint32_t* a, const uint32_t* b) {
    asm volatile("mma.sync.aligned.m16n8k16.row.col.f32.f16.f16.f32 "
        "{%0,%1,%2,%3}, {%4,%5,%6,%7}, {%8,%9}, {%0,%1,%2,%3};"
        : "+f"(d[0]), "+f"(d[1]), "+f"(d[2]), "+f"(d[3])
        : "r"(a[0]), "r"(a[1]), "r"(a[2]), "r"(a[3]), "r"(b[0]), "r"(b[1]));
}

// ---------------- HMMA split-precision GEMM ----------------
// CTA tile 128x128, BK=32, 3 stages, 256 threads (8 warps of 64x32), 2 CTAs/SM.
// smem row = 32 x16 = 64B packed; chunk c of row r at r*64+((c^((r>>1)&3))<<4).
// Stage: Ahi[0,8K) Alo[8K,16K) Bhi[16K,24K) Blo[24K,32K)
static constexpr int STAGE_B = 32768;
static constexpr int SMEM_HG = 3 * STAGE_B;   // 98304 -> 2 CTAs/SM (192KB)

// z decomposition: zi = z>>3, zr = z&7; row offsets = zi*Hi + zr*Lo
// EPI: 0 = fp32*alpha, 2 = fp16 hi of (d*alpha)^2, 3 = fp16 (hi,lo)
// NPROD: 3 = Ahi*Bhi + Ahi*Blo + Alo*Bhi, 2 = Ahi*(Bhi+Blo)
template <int EPI, int NPROD>
__global__ __launch_bounds__(256, 2)
void hgemm3(const uint16_t* __restrict__ Ah, const uint16_t* __restrict__ Al,
            const uint16_t* __restrict__ Bh, const uint16_t* __restrict__ Bl,
            float* __restrict__ Cf, void* __restrict__ Cho, void* __restrict__ Clo,
            int K, int ldc, size_t sC,
            int azHi, int azLo, int bzHi, int bzLo, float alpha)
{
    extern __shared__ char smem[];
    const uint32_t sbase = smem_u32(smem);
    const int tid  = threadIdx.x;
    const int lane = tid & 31;
    const int wid  = tid >> 5;
    const int wm   = wid >> 2;
    const int wn   = wid & 3;
    const int khog = wm;                // de-phase bit
    const int row0 = blockIdx.y * 128;
    const int col0 = blockIdx.x * 128;
    const int z    = blockIdx.z;
    const int zi   = z >> 3, zr = z & 7;
    const int aoff = zi * azHi + zr * azLo;
    const int boff = zi * bzHi + zr * bzLo;

    // ---- loader lanes ----
    const int lr  = tid >> 1;
    const int lcb = (tid & 1) * 2;
    const size_t arow = (size_t)(row0 + aoff + lr);
    const size_t brow = (size_t)(col0 + boff + lr);
    const uint16_t* pAh = Ah + arow * K + lcb * 8;
    const uint16_t* pAl = (NPROD == 3) ? (Al + arow * K + lcb * 8) : pAh;
    const uint16_t* pBh = Bh + brow * K + lcb * 8;
    const uint16_t* pBl = Bl + brow * K + lcb * 8;
    const uint32_t lsw = (uint32_t)((lr >> 1) & 3);
    const uint32_t st1 = lr * 64 + (((uint32_t)lcb ^ lsw) << 4);
    const uint32_t st2 = lr * 64 + ((((uint32_t)lcb + 1u) ^ lsw) << 4);

    auto prefetch = [&](int go, int stage) {
        const uint32_t sb = sbase + (uint32_t)stage * STAGE_B;
        CP16(sb +          st1, pAh + go); CP16(sb +          st2, pAh + go + 8);
        if (NPROD == 3) {
            CP16(sb + 8192u + st1, pAl + go); CP16(sb + 8192u + st2, pAl + go + 8);
        }
        CP16(sb + 16384u + st1, pBh + go); CP16(sb + 16384u + st2, pBh + go + 8);
        CP16(sb + 24576u + st1, pBl + go); CP16(sb + 24576u + st2, pBl + go + 8);
    };

    // ---- fragment addressing ----
    const int lr16  = lane & 15;
    const uint32_t khalf = (uint32_t)(lane >> 4);
    const uint32_t fsw   = (uint32_t)((lr16 >> 1) & 3);
    uint32_t a_base[4], b_base[2];
    #pragma unroll
    for (int mi = 0; mi < 4; mi++) a_base[mi] = (uint32_t)(wm * 64 + mi * 16 + lr16) * 64u;
    #pragma unroll
    for (int g = 0; g < 2; g++)    b_base[g]  = (uint32_t)(wn * 32 + g * 16 + lr16) * 64u;

    float acc[4][4][4];
    #pragma unroll
    for (int mi = 0; mi < 4; mi++)
        #pragma unroll
        for (int nj = 0; nj < 4; nj++)
            #pragma unroll
            for (int q = 0; q < 4; q++) acc[mi][nj][q] = 0.0f;

    // one 16-k slice, term-major MMA order
    auto slice = [&](uint32_t stg, int ks) {
        const uint32_t coff = ((((uint32_t)(ks * 2) + khalf) ^ fsw) << 4);
        uint32_t Bhi[4][2], Blo[4][2];
        #pragma unroll
        for (int g = 0; g < 2; g++) {
            uint32_t q0, q1, q2, q3;
            LDSM4(q0, q1, q2, q3, stg + 16384u + b_base[g] + coff);
            Bhi[2 * g][0] = q0;     Bhi[2 * g][1] = q2;
            Bhi[2 * g + 1][0] = q1; Bhi[2 * g + 1][1] = q3;
            LDSM4(q0, q1, q2, q3, stg + 24576u + b_base[g] + coff);
            Blo[2 * g][0] = q0;     Blo[2 * g][1] = q2;
            Blo[2 * g + 1][0] = q1; Blo[2 * g + 1][1] = q3;
        }
        uint32_t Ahi[4][4];
        #pragma unroll
        for (int mi = 0; mi < 4; mi++)
            LDSM4(Ahi[mi][0], Ahi[mi][1], Ahi[mi][2], Ahi[mi][3],
                  stg + a_base[mi] + coff);

        #pragma unroll
        for (int mi = 0; mi < 4; mi++)
            #pragma unroll
            for (int nj = 0; nj < 4; nj++)
                mmaf16(acc[mi][nj], Ahi[mi], Bhi[nj]);
        #pragma unroll
        for (int mi = 0; mi < 4; mi++)
            #pragma unroll
            for (int nj = 0; nj < 4; nj++)
                mmaf16(acc[mi][nj], Ahi[mi], Blo[nj]);
        if (NPROD == 3) {
            #pragma unroll
            for (int mi = 0; mi < 4; mi++) {
                uint32_t Alo[4];
                LDSM4(Alo[0], Alo[1], Alo[2], Alo[3],
                      stg + 8192u + a_base[mi] + coff);
                #pragma unroll
                for (int nj = 0; nj < 4; nj++)
                    mmaf16(acc[mi][nj], Alo, Bhi[nj]);
            }
        }
    };

    const int nk = K >> 5;

    prefetch(0, 0);  CP_COMMIT();
    prefetch(32, 1); CP_COMMIT();

    int cs = 0, ps = 2, gof = 64;
    for (int kt = 0; kt < nk; kt++) {
        CP_WAIT1();
        __syncthreads();

        const uint32_t stg = sbase + (uint32_t)cs * STAGE_B;
        slice(stg, khog);
        if (kt + 2 < nk) { prefetch(gof, ps); gof += 32; }
        CP_COMMIT();
        slice(stg, 1 - khog);

        cs = (cs == 2) ? 0 : cs + 1;
        ps = (ps == 2) ? 0 : ps + 1;
    }

    // ---- epilogue ----
    const size_t cb = (size_t)z * sC;
    #pragma unroll
    for (int mi = 0; mi < 4; mi++) {
        #pragma unroll
        for (int nj = 0; nj < 4; nj++) {
            const int rg = row0 + wm * 64 + mi * 16 + (lane >> 2);
            const int cg = col0 + wn * 32 + nj * 8 + (lane & 3) * 2;
            float d0 = acc[mi][nj][0] * alpha, d1 = acc[mi][nj][1] * alpha;
            float d2 = acc[mi][nj][2] * alpha, d3 = acc[mi][nj][3] * alpha;
            const size_t i0 = cb + (size_t)rg * ldc + cg;
            const size_t i1 = cb + (size_t)(rg + 8) * ldc + cg;
            if (EPI == 0) {
                *(float2*)(Cf + i0) = make_float2(d0, d1);
                *(float2*)(Cf + i1) = make_float2(d2, d3);
            } else if (EPI == 2) {
                fp16* Ch = (fp16*)Cho;
                __half2 h;
                h.x = __float2half_rn(d0 * d0); h.y = __float2half_rn(d1 * d1);
                *(__half2*)(Ch + i0) = h;
                h.x = __float2half_rn(d2 * d2); h.y = __float2half_rn(d3 * d3);
                *(__half2*)(Ch + i1) = h;
            } else {  // EPI == 3: fp16 (hi, lo)
                fp16* Ch = (fp16*)Cho; fp16* Cl = (fp16*)Clo;
                __half2 h, l;
                h.x = __float2half_rn(d0); h.y = __float2half_rn(d1);
                l.x = __float2half_rn(d0 - __half2float(h.x));
                l.y = __float2half_rn(d1 - __half2float(h.y));
                *(__half2*)(Ch + i0) = h; *(__half2*)(Cl + i0) = l;
                h.x = __float2half_rn(d2); h.y = __float2half_rn(d3);
                l.x = __float2half_rn(d2 - __half2float(h.x));
                l.y = __float2half_rn(d3 - __half2float(h.y));
                *(__half2*)(Ch + i1) = h; *(__half2*)(Cl + i1) = l;
            }
        }
    }
}

// ---------------- conversions ----------------
struct WPtrs3 { const float* p[3]; };   // Wv, W1, W2
struct WPtrs4 { const float* p[4]; };   // Wq1, Wk1, Wq2, Wk2

// y==0: x -> fp16 pair. y==1: Wv -> fp16 hi; Wcat=[W1|-W2] (ld 4096) -> fp16 pair.
__global__ __launch_bounds__(256)
void convert_all(const float* __restrict__ x, WPtrs3 w,
                 fp16* __restrict__ xh, fp16* __restrict__ xl,
                 fp16* __restrict__ Wvh,
                 fp16* __restrict__ Wch, fp16* __restrict__ Wcl)
{
    const size_t stride = (size_t)gridDim.x * blockDim.x;
    size_t i = (size_t)blockIdx.x * blockDim.x + threadIdx.x;
    if (blockIdx.y == 0) {
        for (; i < NTOT; i += stride) {
            float f = x[i];
            fp16 h = __float2half_rn(f);
            xh[i] = h;
            xl[i] = __float2half_rn(f - __half2float(h));
        }
    } else {
        const size_t n = 3 * SSZ;
        for (; i < n; i += stride) {
            if (i < SSZ) {
                Wvh[i] = __float2half_rn(w.p[0][i]);
            } else {
                const size_t j = i - SSZ;
                const size_t u = j >> 12;          // row (4096 cols)
                const int k = (int)(j & 4095);
                float f = (k < SEQ) ? w.p[1][u * SEQ + k]
                                    : -w.p[2][u * SEQ + (k - SEQ)];
                fp16 h = __float2half_rn(f);
                Wch[j] = h;
                Wcl[j] = __float2half_rn(f - __half2float(h));
            }
        }
    }
}

// Transpose Wq1,Wk1,Wq2,Wk2 (fp32 [SEQ,SEQ]) -> fp16 (hi,lo) pairs.
__global__ __launch_bounds__(256)
void transpose_pairs(WPtrs4 w,
                     fp16* __restrict__ WTqh, fp16* __restrict__ WTql,
                     fp16* __restrict__ WTkh, fp16* __restrict__ WTkl)
{
    __shared__ float t[32][33];
    const int z = blockIdx.z;
    const float* src = w.p[z];
    fp16* dh = (z & 1) ? WTkh : WTqh;
    fp16* dl = (z & 1) ? WTkl : WTql;
    const size_t base = (z >> 1) ? SSZ : 0;

    const int tx = threadIdx.x, ty = threadIdx.y;   // 32 x 8
    const int x = blockIdx.x * 32 + tx;
    const int y = blockIdx.y * 32 + ty;
    #pragma unroll
    for (int r = 0; r < 4; r++)
        t[ty + r * 8][tx] = src[(size_t)(y + r * 8) * SEQ + x];
    __syncthreads();
    const int x2 = blockIdx.y * 32 + tx;
    const int y2 = blockIdx.x * 32 + ty;
    #pragma unroll
    for (int r = 0; r < 4; r++) {
        float f = t[tx][ty + r * 8];
        fp16 h = __float2half_rn(f);
        const size_t idx = base + (size_t)(y2 + r * 8) * SEQ + x2;
        dh[idx] = h;
        dl[idx] = __float2half_rn(f - __half2float(h));
    }
}

// softmax of S row r; writes fp16 HI ONLY into Acat[h*S+s][branch*2048 + :]
__global__ __launch_bounds__(256)
void softmax_cat(const float* __restrict__ S, fp16* __restrict__ P)
{
    const int tid = threadIdx.x;
    const int r = blockIdx.x;
    const int branch = r >> 14;           // MROWS = 2^14
    const int hs = r & (MROWS - 1);
    const float* p = S + (size_t)r * SEQ;
    fp16* oh = P + (size_t)hs * 4096 + (size_t)branch * SEQ;
    __shared__ float buf[SEQ];
    __shared__ float red[256];

    float m = -INFINITY;
    for (int i = tid; i < SEQ; i += 256) { float v = p[i]; buf[i] = v; m = fmaxf(m, v); }
    red[tid] = m; __syncthreads();
    for (int s = 128; s > 0; s >>= 1) { if (tid < s) red[tid] = fmaxf(red[tid], red[tid + s]); __syncthreads(); }
    m = red[0]; __syncthreads();

    float sum = 0.0f;
    for (int i = tid; i < SEQ; i += 256) { float e = __expf(buf[i] - m); buf[i] = e; sum += e; }
    red[tid] = sum; __syncthreads();
    for (int s = 128; s > 0; s >>= 1) { if (tid < s) red[tid] += red[tid + s]; __syncthreads(); }
    const float inv = 1.0f / red[0]; __syncthreads();

    for (int i = tid; i < SEQ; i += 256)
        oh[i] = __float2half_rn(buf[i] * inv);
}

// ---------------- host side ----------------
template <typename T>
static T* sym_addr(T* symbol) {
    void* p = nullptr;
    cudaGetSymbolAddress(&p, (const void*)symbol);
    return (T*)p;
}

template <int EPI, int NPROD>
static void launch_g(const void* Ah, const void* Al, int azHi, int azLo,
                     const void* Bh, const void* Bl, int bzHi, int bzLo,
                     int Mrows, int Ncols, int K, int ldc, int batch,
                     float* Cf, void* Cho, void* Clo, size_t sC, float alpha)
{
    cudaFuncSetAttribute((const void*)hgemm3<EPI, NPROD>,
                         cudaFuncAttributeMaxDynamicSharedMemorySize, SMEM_HG);
    dim3 grid(Ncols / 128, Mrows / 128, batch);
    hgemm3<EPI, NPROD><<<grid, 256, SMEM_HG>>>(
        (const uint16_t*)Ah, (const uint16_t*)Al,
        (const uint16_t*)Bh, (const uint16_t*)Bl,
        Cf, Cho, Clo, K, ldc, sC, azHi, azLo, bzHi, bzLo, alpha);
}

extern "C" void kernel_launch(void* const* d_in, const int* in_sizes, int n_in,
                              void* d_out, int out_size)
{
    (void)in_sizes; (void)n_in; (void)out_size;
    const float* x = (const float*)d_in[0];
    WPtrs4 wqk;
    wqk.p[0] = (const float*)d_in[1];   // Wq1
    wqk.p[1] = (const float*)d_in[2];   // Wk1
    wqk.p[2] = (const float*)d_in[3];   // Wq2
    wqk.p[3] = (const float*)d_in[4];   // Wk2
    WPtrs3 wv;
    wv.p[0] = (const float*)d_in[5];    // Wv
    wv.p[1] = (const float*)d_in[6];    // W1
    wv.p[2] = (const float*)d_in[7];    // W2
    float* out = (float*)d_out;

    fp16 *xh = sym_addr(g_xh),   *xl = sym_addr(g_xl);
    fp16 *Wvh = sym_addr(g_Wvh);
    fp16 *Wch = sym_addr(g_Wch), *Wcl = sym_addr(g_Wcl);
    fp16 *WTqh = sym_addr(g_WTqh), *WTql = sym_addr(g_WTql);
    fp16 *WTkh = sym_addr(g_WTkh), *WTkl = sym_addr(g_WTkl);
    fp16 *Nhh = sym_addr(g_Nh),  *Nll = sym_addr(g_Nl);
    fp16 *Thh = sym_addr(g_Th),  *Tll = sym_addr(g_Tl);
    fp16 *Vth = sym_addr(g_Vth), *Vtl = sym_addr(g_Vtl);
    fp16 *Acat = sym_addr(g_Acat);
    fp16 *Cc = sym_addr(g_C);
    float *S = sym_addr(g_S);

    const float scale = 1.0f / sqrtf((float)SEQ);

    // [0] conversions: x (fp16 pair), Wv (fp16 hi), Wcat=[W1|-W2] (fp16 pair)
    convert_all<<<dim3(1024, 2), 256>>>(x, wv, xh, xl, Wvh, Wch, Wcl);

    // [1] transposes: Wq1,Wk1,Wq2,Wk2 -> WTq/WTk fp16 pairs
    transpose_pairs<<<dim3(SEQ / 32, SEQ / 32, 4), dim3(32, 8)>>>(
        wqk, WTqh, WTql, WTkh, WTkl);

    // [2] N_i = WTk_i @ WTq_i^T  (fp16 3-prod -> fp16 pair)
    launch_g<3, 3>(WTkh, WTkl, 0, SEQ, WTqh, WTql, 0, SEQ,
                   SEQ, SEQ, SEQ, SEQ, 2,
                   nullptr, Nhh, Nll, SSZ, 1.0f);

    // [3] T_i = X @ N_i^T  (fp16 2-prod -> fp16 pair)
    launch_g<3, 2>(xh, xh, 0, 0, Nhh, Nll, 0, SEQ,
                   MROWS, SEQ, SEQ, SEQ, 2,
                   nullptr, Thh, Tll, NTOT, 1.0f);

    // [4] Vt[h] = Wv @ X[h]^T  (fp16 2-prod -> fp16 pair)
    launch_g<3, 2>(Wvh, Wvh, 0, 0, xh, xl, 0, SEQ,
                   SEQ, SEQ, SEQ, SEQ, NH,
                   nullptr, Vth, Vtl, SSZ, 1.0f);

    // [5] logits: S[i][h] = scale * T_i[h] @ X[h]^T  (fp16 3-prod -> fp32)
    launch_g<0, 3>(Thh, Tll, MROWS, SEQ, xh, xl, 0, SEQ,
                   SEQ, SEQ, SEQ, SEQ, 2 * NH,
                   S, nullptr, nullptr, SSZ, scale);

    // [6] softmax rows -> Acat fp16 hi-only ([h*S+s][branch*2048+:], ld 4096)
    softmax_cat<<<2 * MROWS, 256>>>(S, Acat);

    // [7] circle[h]*4096 = (64 * Acat[h] @ Wcat^T)^2  (fp16 2-prod, K=4096)
    launch_g<2, 2>(Acat, Acat, 0, SEQ, Wch, Wcl, 0, 0,
                   SEQ, SEQ, 2 * SEQ, SEQ, NH,
                   nullptr, Cc, nullptr, SSZ, 64.0f);

    // [8] out[h] = (1/4096) * circle4096[h] @ Vt[h]^T  (fp16 2-prod -> fp32)
    launch_g<0, 2>(Cc, Cc, 0, SEQ, Vth, Vtl, 0, SEQ,
                   SEQ, SEQ, SEQ, SEQ, NH,
                   out, nullptr, nullptr, SSZ, 1.0f / 4096.0f);
}

// round 16
// speedup vs baseline: 1.5685x; 1.1332x over previous
#include <cuda_runtime.h>
#include <cuda_bf16.h>
#include <cuda_fp16.h>
#include <math.h>
#include <stdint.h>
#include <stddef.h>

// ============================================================================
// biSoftmax on GB300 via HMMA (mma.sync fp16) split-precision GEMMs.
// R16: logits GEMM 3-prod -> 2-prod (A = T hi-only, B = x pair); T stored
//      fp16 hi-only (new EPI=4). Issued tensor work 150 -> 134 product-units.
//      Error model: adds one more ~2^-11 random-sign term -> predicted
//      rel_err ~6.5e-4 (budget 1e-3). Mainloop untouched (58% ceiling).
// All GEMMs are NT: C[m,n] = alpha * sum_k A[m,k] * B[n,k]
// ============================================================================

#define SEQ 2048
#define NH 8
#define MROWS (NH * SEQ)                 // 16384
#define SSZ ((size_t)SEQ * SEQ)          // 2^22
#define NTOT ((size_t)MROWS * SEQ)       // 2^25

typedef __half fp16;

// ---------------- scratch (device globals, allocation-free) ----------------
__device__ fp16 g_xh[NTOT],       g_xl[NTOT];        // x fp16 pair
__device__ fp16 g_Wvh[SSZ];                          // Wv fp16 hi
__device__ fp16 g_Wch[2 * SSZ],   g_Wcl[2 * SSZ];    // Wcat=[W1|-W2] fp16 pair
__device__ fp16 g_WTqh[2 * SSZ],  g_WTql[2 * SSZ];   // Wq1^T, Wq2^T fp16 pair
__device__ fp16 g_WTkh[2 * SSZ],  g_WTkl[2 * SSZ];   // Wk1^T, Wk2^T fp16 pair
__device__ fp16 g_Nh[2 * SSZ],    g_Nl[2 * SSZ];     // N_i fp16 pair
__device__ fp16 g_Th[2 * NTOT];                      // T_i fp16 hi only
__device__ fp16 g_Vth[NTOT],      g_Vtl[NTOT];       // Vt fp16 pair [h][e][t]
__device__ fp16 g_Acat[2 * NTOT];                    // softmax, fp16 hi only
__device__ fp16 g_C[NTOT];                           // circle*4096, fp16 hi
__device__ float g_S[2 * NTOT];                      // logits (fp32)

// ---------------- PTX helpers ----------------
__device__ __forceinline__ uint32_t smem_u32(const void* p) {
    uint32_t a;
    asm("{ .reg .u64 t; cvta.to.shared.u64 t, %1; cvt.u32.u64 %0, t; }" : "=r"(a) : "l"(p));
    return a;
}

#define CP16(dst, src) \
    asm volatile("cp.async.cg.shared.global [%0], [%1], 16;" :: "r"(dst), "l"(src) : "memory")
#define CP_COMMIT() asm volatile("cp.async.commit_group;" ::: "memory")
#define CP_WAIT1()  asm volatile("cp.async.wait_group 1;" ::: "memory")

#define LDSM4(r0, r1, r2, r3, a) \
    asm volatile("ldmatrix.sync.aligned.m8n8.x4.shared.b16 {%0,%1,%2,%3}, [%4];" \
        : "=r"(r0), "=r"(r1), "=r"(r2), "=r"(r3) : "r"(a))

__device__ __forceinline__ void mmaf16(float* d, const uint32_t* a, const uint32_t* b) {
    asm volatile("mma.sync.aligned.m16n8k16.row.col.f32.f16.f16.f32 "
        "{%0,%1,%2,%3}, {%4,%5,%6,%7}, {%8,%9}, {%0,%1,%2,%3};"
        : "+f"(d[0]), "+f"(d[1]), "+f"(d[2]), "+f"(d[3])
        : "r"(a[0]), "r"(a[1]), "r"(a[2]), "r"(a[3]), "r"(b[0]), "r"(b[1]));
}

// ---------------- HMMA split-precision GEMM ----------------
// CTA tile 128x128, BK=32, 3 stages, 256 threads (8 warps of 64x32), 2 CTAs/SM.
// smem row = 32 x16 = 64B packed; chunk c of row r at r*64+((c^((r>>1)&3))<<4).
// Stage: Ahi[0,8K) Alo[8K,16K) Bhi[16K,24K) Blo[24K,32K)
static constexpr int STAGE_B = 32768;
static constexpr int SMEM_HG = 3 * STAGE_B;   // 98304 -> 2 CTAs/SM (192KB)

// z decomposition: zi = z>>3, zr = z&7; row offsets = zi*Hi + zr*Lo
// EPI: 0 = fp32*alpha, 2 = fp16 hi of (d*alpha)^2, 3 = fp16 (hi,lo), 4 = fp16 hi
// NPROD: 3 = Ahi*Bhi + Ahi*Blo + Alo*Bhi, 2 = Ahi*(Bhi+Blo)
template <int EPI, int NPROD>
__global__ __launch_bounds__(256, 2)
void hgemm3(const uint16_t* __restrict__ Ah, const uint16_t* __restrict__ Al,
            const uint16_t* __restrict__ Bh, const uint16_t* __restrict__ Bl,
            float* __restrict__ Cf, void* __restrict__ Cho, void* __restrict__ Clo,
            int K, int ldc, size_t sC,
            int azHi, int azLo, int bzHi, int bzLo, float alpha)
{
    extern __shared__ char smem[];
    const uint32_t sbase = smem_u32(smem);
    const int tid  = threadIdx.x;
    const int lane = tid & 31;
    const int wid  = tid >> 5;
    const int wm   = wid >> 2;
    const int wn   = wid & 3;
    const int khog = wm;                // de-phase bit
    const int row0 = blockIdx.y * 128;
    const int col0 = blockIdx.x * 128;
    const int z    = blockIdx.z;
    const int zi   = z >> 3, zr = z & 7;
    const int aoff = zi * azHi + zr * azLo;
    const int boff = zi * bzHi + zr * bzLo;

    // ---- loader lanes ----
    const int lr  = tid >> 1;
    const int lcb = (tid & 1) * 2;
    const size_t arow = (size_t)(row0 + aoff + lr);
    const size_t brow = (size_t)(col0 + boff + lr);
    const uint16_t* pAh = Ah + arow * K + lcb * 8;
    const uint16_t* pAl = (NPROD == 3) ? (Al + arow * K + lcb * 8) : pAh;
    const uint16_t* pBh = Bh + brow * K + lcb * 8;
    const uint16_t* pBl = Bl + brow * K + lcb * 8;
    const uint32_t lsw = (uint32_t)((lr >> 1) & 3);
    const uint32_t st1 = lr * 64 + (((uint32_t)lcb ^ lsw) << 4);
    const uint32_t st2 = lr * 64 + ((((uint32_t)lcb + 1u) ^ lsw) << 4);

    auto prefetch = [&](int go, int stage) {
        const uint32_t sb = sbase + (uint32_t)stage * STAGE_B;
        CP16(sb +          st1, pAh + go); CP16(sb +          st2, pAh + go + 8);
        if (NPROD == 3) {
            CP16(sb + 8192u + st1, pAl + go); CP16(sb + 8192u + st2, pAl + go + 8);
        }
        CP16(sb + 16384u + st1, pBh + go); CP16(sb + 16384u + st2, pBh + go + 8);
        CP16(sb + 24576u + st1, pBl + go); CP16(sb + 24576u + st2, pBl + go + 8);
    };

    // ---- fragment addressing ----
    const int lr16  = lane & 15;
    const uint32_t khalf = (uint32_t)(lane >> 4);
    const uint32_t fsw   = (uint32_t)((lr16 >> 1) & 3);
    uint32_t a_base[4], b_base[2];
    #pragma unroll
    for (int mi = 0; mi < 4; mi++) a_base[mi] = (uint32_t)(wm * 64 + mi * 16 + lr16) * 64u;
    #pragma unroll
    for (int g = 0; g < 2; g++)    b_base[g]  = (uint32_t)(wn * 32 + g * 16 + lr16) * 64u;

    float acc[4][4][4];
    #pragma unroll
    for (int mi = 0; mi < 4; mi++)
        #pragma unroll
        for (int nj = 0; nj < 4; nj++)
            #pragma unroll
            for (int q = 0; q < 4; q++) acc[mi][nj][q] = 0.0f;

    // one 16-k slice, term-major MMA order
    auto slice = [&](uint32_t stg, int ks) {
        const uint32_t coff = ((((uint32_t)(ks * 2) + khalf) ^ fsw) << 4);
        uint32_t Bhi[4][2], Blo[4][2];
        #pragma unroll
        for (int g = 0; g < 2; g++) {
            uint32_t q0, q1, q2, q3;
            LDSM4(q0, q1, q2, q3, stg + 16384u + b_base[g] + coff);
            Bhi[2 * g][0] = q0;     Bhi[2 * g][1] = q2;
            Bhi[2 * g + 1][0] = q1; Bhi[2 * g + 1][1] = q3;
            LDSM4(q0, q1, q2, q3, stg + 24576u + b_base[g] + coff);
            Blo[2 * g][0] = q0;     Blo[2 * g][1] = q2;
            Blo[2 * g + 1][0] = q1; Blo[2 * g + 1][1] = q3;
        }
        uint32_t Ahi[4][4];
        #pragma unroll
        for (int mi = 0; mi < 4; mi++)
            LDSM4(Ahi[mi][0], Ahi[mi][1], Ahi[mi][2], Ahi[mi][3],
                  stg + a_base[mi] + coff);

        #pragma unroll
        for (int mi = 0; mi < 4; mi++)
            #pragma unroll
            for (int nj = 0; nj < 4; nj++)
                mmaf16(acc[mi][nj], Ahi[mi], Bhi[nj]);
        #pragma unroll
        for (int mi = 0; mi < 4; mi++)
            #pragma unroll
            for (int nj = 0; nj < 4; nj++)
                mmaf16(acc[mi][nj], Ahi[mi], Blo[nj]);
        if (NPROD == 3) {
            #pragma unroll
            for (int mi = 0; mi < 4; mi++) {
                uint32_t Alo[4];
                LDSM4(Alo[0], Alo[1], Alo[2], Alo[3],
                      stg + 8192u + a_base[mi] + coff);
                #pragma unroll
                for (int nj = 0; nj < 4; nj++)
                    mmaf16(acc[mi][nj], Alo, Bhi[nj]);
            }
        }
    };

    const int nk = K >> 5;

    prefetch(0, 0);  CP_COMMIT();
    prefetch(32, 1); CP_COMMIT();

    int cs = 0, ps = 2, gof = 64;
    for (int kt = 0; kt < nk; kt++) {
        CP_WAIT1();
        __syncthreads();

        const uint32_t stg = sbase + (uint32_t)cs * STAGE_B;
        slice(stg, khog);
        if (kt + 2 < nk) { prefetch(gof, ps); gof += 32; }
        CP_COMMIT();
        slice(stg, 1 - khog);

        cs = (cs == 2) ? 0 : cs + 1;
        ps = (ps == 2) ? 0 : ps + 1;
    }

    // ---- epilogue ----
    const size_t cb = (size_t)z * sC;
    #pragma unroll
    for (int mi = 0; mi < 4; mi++) {
        #pragma unroll
        for (int nj = 0; nj < 4; nj++) {
            const int rg = row0 + wm * 64 + mi * 16 + (lane >> 2);
            const int cg = col0 + wn * 32 + nj * 8 + (lane & 3) * 2;
            float d0 = acc[mi][nj][0] * alpha, d1 = acc[mi][nj][1] * alpha;
            float d2 = acc[mi][nj][2] * alpha, d3 = acc[mi][nj][3] * alpha;
            const size_t i0 = cb + (size_t)rg * ldc + cg;
            const size_t i1 = cb + (size_t)(rg + 8) * ldc + cg;
            if (EPI == 0) {
                *(float2*)(Cf + i0) = make_float2(d0, d1);
                *(float2*)(Cf + i1) = make_float2(d2, d3);
            } else if (EPI == 2) {
                fp16* Ch = (fp16*)Cho;
                __half2 h;
                h.x = __float2half_rn(d0 * d0); h.y = __float2half_rn(d1 * d1);
                *(__half2*)(Ch + i0) = h;
                h.x = __float2half_rn(d2 * d2); h.y = __float2half_rn(d3 * d3);
                *(__half2*)(Ch + i1) = h;
            } else if (EPI == 3) {  // fp16 (hi, lo)
                fp16* Ch = (fp16*)Cho; fp16* Cl = (fp16*)Clo;
                __half2 h, l;
                h.x = __float2half_rn(d0); h.y = __float2half_rn(d1);
                l.x = __float2half_rn(d0 - __half2float(h.x));
                l.y = __float2half_rn(d1 - __half2float(h.y));
                *(__half2*)(Ch + i0) = h; *(__half2*)(Cl + i0) = l;
                h.x = __float2half_rn(d2); h.y = __float2half_rn(d3);
                l.x = __float2half_rn(d2 - __half2float(h.x));
                l.y = __float2half_rn(d3 - __half2float(h.y));
                *(__half2*)(Ch + i1) = h; *(__half2*)(Cl + i1) = l;
            } else {  // EPI == 4: fp16 hi only
                fp16* Ch = (fp16*)Cho;
                __half2 h;
                h.x = __float2half_rn(d0); h.y = __float2half_rn(d1);
                *(__half2*)(Ch + i0) = h;
                h.x = __float2half_rn(d2); h.y = __float2half_rn(d3);
                *(__half2*)(Ch + i1) = h;
            }
        }
    }
}

// ---------------- conversions ----------------
struct WPtrs3 { const float* p[3]; };   // Wv, W1, W2
struct WPtrs4 { const float* p[4]; };   // Wq1, Wk1, Wq2, Wk2

// y==0: x -> fp16 pair. y==1: Wv -> fp16 hi; Wcat=[W1|-W2] (ld 4096) -> fp16 pair.
__global__ __launch_bounds__(256)
void convert_all(const float* __restrict__ x, WPtrs3 w,
                 fp16* __restrict__ xh, fp16* __restrict__ xl,
                 fp16* __restrict__ Wvh,
                 fp16* __restrict__ Wch, fp16* __restrict__ Wcl)
{
    const size_t stride = (size_t)gridDim.x * blockDim.x;
    size_t i = (size_t)blockIdx.x * blockDim.x + threadIdx.x;
    if (blockIdx.y == 0) {
        for (; i < NTOT; i += stride) {
            float f = x[i];
            fp16 h = __float2half_rn(f);
            xh[i] = h;
            xl[i] = __float2half_rn(f - __half2float(h));
        }
    } else {
        const size_t n = 3 * SSZ;
        for (; i < n; i += stride) {
            if (i < SSZ) {
                Wvh[i] = __float2half_rn(w.p[0][i]);
            } else {
                const size_t j = i - SSZ;
                const size_t u = j >> 12;          // row (4096 cols)
                const int k = (int)(j & 4095);
                float f = (k < SEQ) ? w.p[1][u * SEQ + k]
                                    : -w.p[2][u * SEQ + (k - SEQ)];
                fp16 h = __float2half_rn(f);
                Wch[j] = h;
                Wcl[j] = __float2half_rn(f - __half2float(h));
            }
        }
    }
}

// Transpose Wq1,Wk1,Wq2,Wk2 (fp32 [SEQ,SEQ]) -> fp16 (hi,lo) pairs.
__global__ __launch_bounds__(256)
void transpose_pairs(WPtrs4 w,
                     fp16* __restrict__ WTqh, fp16* __restrict__ WTql,
                     fp16* __restrict__ WTkh, fp16* __restrict__ WTkl)
{
    __shared__ float t[32][33];
    const int z = blockIdx.z;
    const float* src = w.p[z];
    fp16* dh = (z & 1) ? WTkh : WTqh;
    fp16* dl = (z & 1) ? WTkl : WTql;
    const size_t base = (z >> 1) ? SSZ : 0;

    const int tx = threadIdx.x, ty = threadIdx.y;   // 32 x 8
    const int x = blockIdx.x * 32 + tx;
    const int y = blockIdx.y * 32 + ty;
    #pragma unroll
    for (int r = 0; r < 4; r++)
        t[ty + r * 8][tx] = src[(size_t)(y + r * 8) * SEQ + x];
    __syncthreads();
    const int x2 = blockIdx.y * 32 + tx;
    const int y2 = blockIdx.x * 32 + ty;
    #pragma unroll
    for (int r = 0; r < 4; r++) {
        float f = t[tx][ty + r * 8];
        fp16 h = __float2half_rn(f);
        const size_t idx = base + (size_t)(y2 + r * 8) * SEQ + x2;
        dh[idx] = h;
        dl[idx] = __float2half_rn(f - __half2float(h));
    }
}

// softmax of S row r; writes fp16 HI ONLY into Acat[h*S+s][branch*2048 + :]
__global__ __launch_bounds__(256)
void softmax_cat(const float* __restrict__ S, fp16* __restrict__ P)
{
    const int tid = threadIdx.x;
    const int r = blockIdx.x;
    const int branch = r >> 14;           // MROWS = 2^14
    const int hs = r & (MROWS - 1);
    const float* p = S + (size_t)r * SEQ;
    fp16* oh = P + (size_t)hs * 4096 + (size_t)branch * SEQ;
    __shared__ float buf[SEQ];
    __shared__ float red[256];

    float m = -INFINITY;
    for (int i = tid; i < SEQ; i += 256) { float v = p[i]; buf[i] = v; m = fmaxf(m, v); }
    red[tid] = m; __syncthreads();
    for (int s = 128; s > 0; s >>= 1) { if (tid < s) red[tid] = fmaxf(red[tid], red[tid + s]); __syncthreads(); }
    m = red[0]; __syncthreads();

    float sum = 0.0f;
    for (int i = tid; i < SEQ; i += 256) { float e = __expf(buf[i] - m); buf[i] = e; sum += e; }
    red[tid] = sum; __syncthreads();
    for (int s = 128; s > 0; s >>= 1) { if (tid < s) red[tid] += red[tid + s]; __syncthreads(); }
    const float inv = 1.0f / red[0]; __syncthreads();

    for (int i = tid; i < SEQ; i += 256)
        oh[i] = __float2half_rn(buf[i] * inv);
}

// ---------------- host side ----------------
template <typename T>
static T* sym_addr(T* symbol) {
    void* p = nullptr;
    cudaGetSymbolAddress(&p, (const void*)symbol);
    return (T*)p;
}

template <int EPI, int NPROD>
static void launch_g(const void* Ah, const void* Al, int azHi, int azLo,
                     const void* Bh, const void* Bl, int bzHi, int bzLo,
                     int Mrows, int Ncols, int K, int ldc, int batch,
                     float* Cf, void* Cho, void* Clo, size_t sC, float alpha)
{
    cudaFuncSetAttribute((const void*)hgemm3<EPI, NPROD>,
                         cudaFuncAttributeMaxDynamicSharedMemorySize, SMEM_HG);
    dim3 grid(Ncols / 128, Mrows / 128, batch);
    hgemm3<EPI, NPROD><<<grid, 256, SMEM_HG>>>(
        (const uint16_t*)Ah, (const uint16_t*)Al,
        (const uint16_t*)Bh, (const uint16_t*)Bl,
        Cf, Cho, Clo, K, ldc, sC, azHi, azLo, bzHi, bzLo, alpha);
}

extern "C" void kernel_launch(void* const* d_in, const int* in_sizes, int n_in,
                              void* d_out, int out_size)
{
    (void)in_sizes; (void)n_in; (void)out_size;
    const float* x = (const float*)d_in[0];
    WPtrs4 wqk;
    wqk.p[0] = (const float*)d_in[1];   // Wq1
    wqk.p[1] = (const float*)d_in[2];   // Wk1
    wqk.p[2] = (const float*)d_in[3];   // Wq2
    wqk.p[3] = (const float*)d_in[4];   // Wk2
    WPtrs3 wv;
    wv.p[0] = (const float*)d_in[5];    // Wv
    wv.p[1] = (const float*)d_in[6];    // W1
    wv.p[2] = (const float*)d_in[7];    // W2
    float* out = (float*)d_out;

    fp16 *xh = sym_addr(g_xh),   *xl = sym_addr(g_xl);
    fp16 *Wvh = sym_addr(g_Wvh);
    fp16 *Wch = sym_addr(g_Wch), *Wcl = sym_addr(g_Wcl);
    fp16 *WTqh = sym_addr(g_WTqh), *WTql = sym_addr(g_WTql);
    fp16 *WTkh = sym_addr(g_WTkh), *WTkl = sym_addr(g_WTkl);
    fp16 *Nhh = sym_addr(g_Nh),  *Nll = sym_addr(g_Nl);
    fp16 *Thh = sym_addr(g_Th);
    fp16 *Vth = sym_addr(g_Vth), *Vtl = sym_addr(g_Vtl);
    fp16 *Acat = sym_addr(g_Acat);
    fp16 *Cc = sym_addr(g_C);
    float *S = sym_addr(g_S);

    const float scale = 1.0f / sqrtf((float)SEQ);

    // [0] conversions: x (fp16 pair), Wv (fp16 hi), Wcat=[W1|-W2] (fp16 pair)
    convert_all<<<dim3(1024, 2), 256>>>(x, wv, xh, xl, Wvh, Wch, Wcl);

    // [1] transposes: Wq1,Wk1,Wq2,Wk2 -> WTq/WTk fp16 pairs
    transpose_pairs<<<dim3(SEQ / 32, SEQ / 32, 4), dim3(32, 8)>>>(
        wqk, WTqh, WTql, WTkh, WTkl);

    // [2] N_i = WTk_i @ WTq_i^T  (fp16 3-prod -> fp16 pair)
    launch_g<3, 3>(WTkh, WTkl, 0, SEQ, WTqh, WTql, 0, SEQ,
                   SEQ, SEQ, SEQ, SEQ, 2,
                   nullptr, Nhh, Nll, SSZ, 1.0f);

    // [3] T_i = X @ N_i^T  (fp16 2-prod -> fp16 hi only)
    launch_g<4, 2>(xh, xh, 0, 0, Nhh, Nll, 0, SEQ,
                   MROWS, SEQ, SEQ, SEQ, 2,
                   nullptr, Thh, nullptr, NTOT, 1.0f);

    // [4] Vt[h] = Wv @ X[h]^T  (fp16 2-prod -> fp16 pair)
    launch_g<3, 2>(Wvh, Wvh, 0, 0, xh, xl, 0, SEQ,
                   SEQ, SEQ, SEQ, SEQ, NH,
                   nullptr, Vth, Vtl, SSZ, 1.0f);

    // [5] logits: S[i][h] = scale * T_i[h] @ X[h]^T  (fp16 2-prod, A=T hi)
    launch_g<0, 2>(Thh, Thh, MROWS, SEQ, xh, xl, 0, SEQ,
                   SEQ, SEQ, SEQ, SEQ, 2 * NH,
                   S, nullptr, nullptr, SSZ, scale);

    // [6] softmax rows -> Acat fp16 hi-only ([h*S+s][branch*2048+:], ld 4096)
    softmax_cat<<<2 * MROWS, 256>>>(S, Acat);

    // [7] circle[h]*4096 = (64 * Acat[h] @ Wcat^T)^2  (fp16 2-prod, K=4096)
    launch_g<2, 2>(Acat, Acat, 0, SEQ, Wch, Wcl, 0, 0,
                   SEQ, SEQ, 2 * SEQ, SEQ, NH,
                   nullptr, Cc, nullptr, SSZ, 64.0f);

    // [8] out[h] = (1/4096) * circle4096[h] @ Vt[h]^T  (fp16 2-prod -> fp32)
    launch_g<0, 2>(Cc, Cc, 0, SEQ, Vth, Vtl, 0, SEQ,
                   SEQ, SEQ, SEQ, SEQ, NH,
                   out, nullptr, nullptr, SSZ, 1.0f / 4096.0f);
}

// round 17
// speedup vs baseline: 2.0166x; 1.2857x over previous
#include <cuda_runtime.h>
#include <cuda_bf16.h>
#include <cuda_fp16.h>
#include <math.h>
#include <stdint.h>
#include <stddef.h>

// ============================================================================
// biSoftmax on GB300 via HMMA (mma.sync fp16) split-precision GEMMs.
// R17: three more 2^-11 truncations (each measured ~2.4e-4 RMS in R16):
//      logits -> 1-prod (A=T hi, B=x hi), Vt -> 1-prod plain fp16,
//      out -> 1-prod (B=Vt hi). Issued tensor work 134 -> 102 product-units.
//      T and circle stay 2-prod; N stays 3-prod. Predicted rel_err ~6.6e-4.
// All GEMMs are NT: C[m,n] = alpha * sum_k A[m,k] * B[n,k]
// ============================================================================

#define SEQ 2048
#define NH 8
#define MROWS (NH * SEQ)                 // 16384
#define SSZ ((size_t)SEQ * SEQ)          // 2^22
#define NTOT ((size_t)MROWS * SEQ)       // 2^25

typedef __half fp16;

// ---------------- scratch (device globals, allocation-free) ----------------
__device__ fp16 g_xh[NTOT],       g_xl[NTOT];        // x fp16 pair
__device__ fp16 g_Wvh[SSZ];                          // Wv fp16 hi
__device__ fp16 g_Wch[2 * SSZ],   g_Wcl[2 * SSZ];    // Wcat=[W1|-W2] fp16 pair
__device__ fp16 g_WTqh[2 * SSZ],  g_WTql[2 * SSZ];   // Wq1^T, Wq2^T fp16 pair
__device__ fp16 g_WTkh[2 * SSZ],  g_WTkl[2 * SSZ];   // Wk1^T, Wk2^T fp16 pair
__device__ fp16 g_Nh[2 * SSZ],    g_Nl[2 * SSZ];     // N_i fp16 pair
__device__ fp16 g_Th[2 * NTOT];                      // T_i fp16 hi only
__device__ fp16 g_Vth[NTOT];                         // Vt fp16 hi [h][e][t]
__device__ fp16 g_Acat[2 * NTOT];                    // softmax, fp16 hi only
__device__ fp16 g_C[NTOT];                           // circle*4096, fp16 hi
__device__ float g_S[2 * NTOT];                      // logits (fp32)

// ---------------- PTX helpers ----------------
__device__ __forceinline__ uint32_t smem_u32(const void* p) {
    uint32_t a;
    asm("{ .reg .u64 t; cvta.to.shared.u64 t, %1; cvt.u32.u64 %0, t; }" : "=r"(a) : "l"(p));
    return a;
}

#define CP16(dst, src) \
    asm volatile("cp.async.cg.shared.global [%0], [%1], 16;" :: "r"(dst), "l"(src) : "memory")
#define CP_COMMIT() asm volatile("cp.async.commit_group;" ::: "memory")
#define CP_WAIT1()  asm volatile("cp.async.wait_group 1;" ::: "memory")

#define LDSM4(r0, r1, r2, r3, a) \
    asm volatile("ldmatrix.sync.aligned.m8n8.x4.shared.b16 {%0,%1,%2,%3}, [%4];" \
        : "=r"(r0), "=r"(r1), "=r"(r2), "=r"(r3) : "r"(a))

__device__ __forceinline__ void mmaf16(float* d, const uint32_t* a, const uint32_t* b) {
    asm volatile("mma.sync.aligned.m16n8k16.row.col.f32.f16.f16.f32 "
        "{%0,%1,%2,%3}, {%4,%5,%6,%7}, {%8,%9}, {%0,%1,%2,%3};"
        : "+f"(d[0]), "+f"(d[1]), "+f"(d[2]), "+f"(d[3])
        : "r"(a[0]), "r"(a[1]), "r"(a[2]), "r"(a[3]), "r"(b[0]), "r"(b[1]));
}

// ---------------- HMMA split-precision GEMM ----------------
// CTA tile 128x128, BK=32, 3 stages, 256 threads (8 warps of 64x32), 2 CTAs/SM.
// smem row = 32 x16 = 64B packed; chunk c of row r at r*64+((c^((r>>1)&3))<<4).
// Stage: Ahi[0,8K) Alo[8K,16K) Bhi[16K,24K) Blo[24K,32K)
static constexpr int STAGE_B = 32768;
static constexpr int SMEM_HG = 3 * STAGE_B;   // 98304 -> 2 CTAs/SM (192KB)

// z decomposition: zi = z>>3, zr = z&7; row offsets = zi*Hi + zr*Lo
// EPI: 0 = fp32*alpha, 2 = fp16 hi of (d*alpha)^2, 3 = fp16 (hi,lo), 4 = fp16 hi
// NPROD: 3 = Ahi*Bhi+Ahi*Blo+Alo*Bhi, 2 = Ahi*(Bhi+Blo), 1 = Ahi*Bhi
template <int EPI, int NPROD>
__global__ __launch_bounds__(256, 2)
void hgemm3(const uint16_t* __restrict__ Ah, const uint16_t* __restrict__ Al,
            const uint16_t* __restrict__ Bh, const uint16_t* __restrict__ Bl,
            float* __restrict__ Cf, void* __restrict__ Cho, void* __restrict__ Clo,
            int K, int ldc, size_t sC,
            int azHi, int azLo, int bzHi, int bzLo, float alpha)
{
    extern __shared__ char smem[];
    const uint32_t sbase = smem_u32(smem);
    const int tid  = threadIdx.x;
    const int lane = tid & 31;
    const int wid  = tid >> 5;
    const int wm   = wid >> 2;
    const int wn   = wid & 3;
    const int khog = wm;                // de-phase bit
    const int row0 = blockIdx.y * 128;
    const int col0 = blockIdx.x * 128;
    const int z    = blockIdx.z;
    const int zi   = z >> 3, zr = z & 7;
    const int aoff = zi * azHi + zr * azLo;
    const int boff = zi * bzHi + zr * bzLo;

    // ---- loader lanes ----
    const int lr  = tid >> 1;
    const int lcb = (tid & 1) * 2;
    const size_t arow = (size_t)(row0 + aoff + lr);
    const size_t brow = (size_t)(col0 + boff + lr);
    const uint16_t* pAh = Ah + arow * K + lcb * 8;
    const uint16_t* pAl = (NPROD == 3) ? (Al + arow * K + lcb * 8) : pAh;
    const uint16_t* pBh = Bh + brow * K + lcb * 8;
    const uint16_t* pBl = (NPROD >= 2) ? (Bl + brow * K + lcb * 8) : pBh;
    const uint32_t lsw = (uint32_t)((lr >> 1) & 3);
    const uint32_t st1 = lr * 64 + (((uint32_t)lcb ^ lsw) << 4);
    const uint32_t st2 = lr * 64 + ((((uint32_t)lcb + 1u) ^ lsw) << 4);

    auto prefetch = [&](int go, int stage) {
        const uint32_t sb = sbase + (uint32_t)stage * STAGE_B;
        CP16(sb +          st1, pAh + go); CP16(sb +          st2, pAh + go + 8);
        if (NPROD == 3) {
            CP16(sb + 8192u + st1, pAl + go); CP16(sb + 8192u + st2, pAl + go + 8);
        }
        CP16(sb + 16384u + st1, pBh + go); CP16(sb + 16384u + st2, pBh + go + 8);
        if (NPROD >= 2) {
            CP16(sb + 24576u + st1, pBl + go); CP16(sb + 24576u + st2, pBl + go + 8);
        }
    };

    // ---- fragment addressing ----
    const int lr16  = lane & 15;
    const uint32_t khalf = (uint32_t)(lane >> 4);
    const uint32_t fsw   = (uint32_t)((lr16 >> 1) & 3);
    uint32_t a_base[4], b_base[2];
    #pragma unroll
    for (int mi = 0; mi < 4; mi++) a_base[mi] = (uint32_t)(wm * 64 + mi * 16 + lr16) * 64u;
    #pragma unroll
    for (int g = 0; g < 2; g++)    b_base[g]  = (uint32_t)(wn * 32 + g * 16 + lr16) * 64u;

    float acc[4][4][4];
    #pragma unroll
    for (int mi = 0; mi < 4; mi++)
        #pragma unroll
        for (int nj = 0; nj < 4; nj++)
            #pragma unroll
            for (int q = 0; q < 4; q++) acc[mi][nj][q] = 0.0f;

    // one 16-k slice, term-major MMA order
    auto slice = [&](uint32_t stg, int ks) {
        const uint32_t coff = ((((uint32_t)(ks * 2) + khalf) ^ fsw) << 4);
        uint32_t Bhi[4][2], Blo[4][2];
        #pragma unroll
        for (int g = 0; g < 2; g++) {
            uint32_t q0, q1, q2, q3;
            LDSM4(q0, q1, q2, q3, stg + 16384u + b_base[g] + coff);
            Bhi[2 * g][0] = q0;     Bhi[2 * g][1] = q2;
            Bhi[2 * g + 1][0] = q1; Bhi[2 * g + 1][1] = q3;
            if (NPROD >= 2) {
                LDSM4(q0, q1, q2, q3, stg + 24576u + b_base[g] + coff);
                Blo[2 * g][0] = q0;     Blo[2 * g][1] = q2;
                Blo[2 * g + 1][0] = q1; Blo[2 * g + 1][1] = q3;
            }
        }
        uint32_t Ahi[4][4];
        #pragma unroll
        for (int mi = 0; mi < 4; mi++)
            LDSM4(Ahi[mi][0], Ahi[mi][1], Ahi[mi][2], Ahi[mi][3],
                  stg + a_base[mi] + coff);

        #pragma unroll
        for (int mi = 0; mi < 4; mi++)
            #pragma unroll
            for (int nj = 0; nj < 4; nj++)
                mmaf16(acc[mi][nj], Ahi[mi], Bhi[nj]);
        if (NPROD >= 2) {
            #pragma unroll
            for (int mi = 0; mi < 4; mi++)
                #pragma unroll
                for (int nj = 0; nj < 4; nj++)
                    mmaf16(acc[mi][nj], Ahi[mi], Blo[nj]);
        }
        if (NPROD == 3) {
            #pragma unroll
            for (int mi = 0; mi < 4; mi++) {
                uint32_t Alo[4];
                LDSM4(Alo[0], Alo[1], Alo[2], Alo[3],
                      stg + 8192u + a_base[mi] + coff);
                #pragma unroll
                for (int nj = 0; nj < 4; nj++)
                    mmaf16(acc[mi][nj], Alo, Bhi[nj]);
            }
        }
    };

    const int nk = K >> 5;

    prefetch(0, 0);  CP_COMMIT();
    prefetch(32, 1); CP_COMMIT();

    int cs = 0, ps = 2, gof = 64;
    for (int kt = 0; kt < nk; kt++) {
        CP_WAIT1();
        __syncthreads();

        const uint32_t stg = sbase + (uint32_t)cs * STAGE_B;
        slice(stg, khog);
        if (kt + 2 < nk) { prefetch(gof, ps); gof += 32; }
        CP_COMMIT();
        slice(stg, 1 - khog);

        cs = (cs == 2) ? 0 : cs + 1;
        ps = (ps == 2) ? 0 : ps + 1;
    }

    // ---- epilogue ----
    const size_t cb = (size_t)z * sC;
    #pragma unroll
    for (int mi = 0; mi < 4; mi++) {
        #pragma unroll
        for (int nj = 0; nj < 4; nj++) {
            const int rg = row0 + wm * 64 + mi * 16 + (lane >> 2);
            const int cg = col0 + wn * 32 + nj * 8 + (lane & 3) * 2;
            float d0 = acc[mi][nj][0] * alpha, d1 = acc[mi][nj][1] * alpha;
            float d2 = acc[mi][nj][2] * alpha, d3 = acc[mi][nj][3] * alpha;
            const size_t i0 = cb + (size_t)rg * ldc + cg;
            const size_t i1 = cb + (size_t)(rg + 8) * ldc + cg;
            if (EPI == 0) {
                *(float2*)(Cf + i0) = make_float2(d0, d1);
                *(float2*)(Cf + i1) = make_float2(d2, d3);
            } else if (EPI == 2) {
                fp16* Ch = (fp16*)Cho;
                __half2 h;
                h.x = __float2half_rn(d0 * d0); h.y = __float2half_rn(d1 * d1);
                *(__half2*)(Ch + i0) = h;
                h.x = __float2half_rn(d2 * d2); h.y = __float2half_rn(d3 * d3);
                *(__half2*)(Ch + i1) = h;
            } else if (EPI == 3) {  // fp16 (hi, lo)
                fp16* Ch = (fp16*)Cho; fp16* Cl = (fp16*)Clo;
                __half2 h, l;
                h.x = __float2half_rn(d0); h.y = __float2half_rn(d1);
                l.x = __float2half_rn(d0 - __half2float(h.x));
                l.y = __float2half_rn(d1 - __half2float(h.y));
                *(__half2*)(Ch + i0) = h; *(__half2*)(Cl + i0) = l;
                h.x = __float2half_rn(d2); h.y = __float2half_rn(d3);
                l.x = __float2half_rn(d2 - __half2float(h.x));
                l.y = __float2half_rn(d3 - __half2float(h.y));
                *(__half2*)(Ch + i1) = h; *(__half2*)(Cl + i1) = l;
            } else {  // EPI == 4: fp16 hi only
                fp16* Ch = (fp16*)Cho;
                __half2 h;
                h.x = __float2half_rn(d0); h.y = __float2half_rn(d1);
                *(__half2*)(Ch + i0) = h;
                h.x = __float2half_rn(d2); h.y = __float2half_rn(d3);
                *(__half2*)(Ch + i1) = h;
            }
        }
    }
}

// ---------------- conversions ----------------
struct WPtrs3 { const float* p[3]; };   // Wv, W1, W2
struct WPtrs4 { const float* p[4]; };   // Wq1, Wk1, Wq2, Wk2

// y==0: x -> fp16 pair. y==1: Wv -> fp16 hi; Wcat=[W1|-W2] (ld 4096) -> fp16 pair.
__global__ __launch_bounds__(256)
void convert_all(const float* __restrict__ x, WPtrs3 w,
                 fp16* __restrict__ xh, fp16* __restrict__ xl,
                 fp16* __restrict__ Wvh,
                 fp16* __restrict__ Wch, fp16* __restrict__ Wcl)
{
    const size_t stride = (size_t)gridDim.x * blockDim.x;
    size_t i = (size_t)blockIdx.x * blockDim.x + threadIdx.x;
    if (blockIdx.y == 0) {
        for (; i < NTOT; i += stride) {
            float f = x[i];
            fp16 h = __float2half_rn(f);
            xh[i] = h;
            xl[i] = __float2half_rn(f - __half2float(h));
        }
    } else {
        const size_t n = 3 * SSZ;
        for (; i < n; i += stride) {
            if (i < SSZ) {
                Wvh[i] = __float2half_rn(w.p[0][i]);
            } else {
                const size_t j = i - SSZ;
                const size_t u = j >> 12;          // row (4096 cols)
                const int k = (int)(j & 4095);
                float f = (k < SEQ) ? w.p[1][u * SEQ + k]
                                    : -w.p[2][u * SEQ + (k - SEQ)];
                fp16 h = __float2half_rn(f);
                Wch[j] = h;
                Wcl[j] = __float2half_rn(f - __half2float(h));
            }
        }
    }
}

// Transpose Wq1,Wk1,Wq2,Wk2 (fp32 [SEQ,SEQ]) -> fp16 (hi,lo) pairs.
__global__ __launch_bounds__(256)
void transpose_pairs(WPtrs4 w,
                     fp16* __restrict__ WTqh, fp16* __restrict__ WTql,
                     fp16* __restrict__ WTkh, fp16* __restrict__ WTkl)
{
    __shared__ float t[32][33];
    const int z = blockIdx.z;
    const float* src = w.p[z];
    fp16* dh = (z & 1) ? WTkh : WTqh;
    fp16* dl = (z & 1) ? WTkl : WTql;
    const size_t base = (z >> 1) ? SSZ : 0;

    const int tx = threadIdx.x, ty = threadIdx.y;   // 32 x 8
    const int x = blockIdx.x * 32 + tx;
    const int y = blockIdx.y * 32 + ty;
    #pragma unroll
    for (int r = 0; r < 4; r++)
        t[ty + r * 8][tx] = src[(size_t)(y + r * 8) * SEQ + x];
    __syncthreads();
    const int x2 = blockIdx.y * 32 + tx;
    const int y2 = blockIdx.x * 32 + ty;
    #pragma unroll
    for (int r = 0; r < 4; r++) {
        float f = t[tx][ty + r * 8];
        fp16 h = __float2half_rn(f);
        const size_t idx = base + (size_t)(y2 + r * 8) * SEQ + x2;
        dh[idx] = h;
        dl[idx] = __float2half_rn(f - __half2float(h));
    }
}

// softmax of S row r; writes fp16 HI ONLY into Acat[h*S+s][branch*2048 + :]
__global__ __launch_bounds__(256)
void softmax_cat(const float* __restrict__ S, fp16* __restrict__ P)
{
    const int tid = threadIdx.x;
    const int r = blockIdx.x;
    const int branch = r >> 14;           // MROWS = 2^14
    const int hs = r & (MROWS - 1);
    const float* p = S + (size_t)r * SEQ;
    fp16* oh = P + (size_t)hs * 4096 + (size_t)branch * SEQ;
    __shared__ float buf[SEQ];
    __shared__ float red[256];

    float m = -INFINITY;
    for (int i = tid; i < SEQ; i += 256) { float v = p[i]; buf[i] = v; m = fmaxf(m, v); }
    red[tid] = m; __syncthreads();
    for (int s = 128; s > 0; s >>= 1) { if (tid < s) red[tid] = fmaxf(red[tid], red[tid + s]); __syncthreads(); }
    m = red[0]; __syncthreads();

    float sum = 0.0f;
    for (int i = tid; i < SEQ; i += 256) { float e = __expf(buf[i] - m); buf[i] = e; sum += e; }
    red[tid] = sum; __syncthreads();
    for (int s = 128; s > 0; s >>= 1) { if (tid < s) red[tid] += red[tid + s]; __syncthreads(); }
    const float inv = 1.0f / red[0]; __syncthreads();

    for (int i = tid; i < SEQ; i += 256)
        oh[i] = __float2half_rn(buf[i] * inv);
}

// ---------------- host side ----------------
template <typename T>
static T* sym_addr(T* symbol) {
    void* p = nullptr;
    cudaGetSymbolAddress(&p, (const void*)symbol);
    return (T*)p;
}

template <int EPI, int NPROD>
static void launch_g(const void* Ah, const void* Al, int azHi, int azLo,
                     const void* Bh, const void* Bl, int bzHi, int bzLo,
                     int Mrows, int Ncols, int K, int ldc, int batch,
                     float* Cf, void* Cho, void* Clo, size_t sC, float alpha)
{
    cudaFuncSetAttribute((const void*)hgemm3<EPI, NPROD>,
                         cudaFuncAttributeMaxDynamicSharedMemorySize, SMEM_HG);
    dim3 grid(Ncols / 128, Mrows / 128, batch);
    hgemm3<EPI, NPROD><<<grid, 256, SMEM_HG>>>(
        (const uint16_t*)Ah, (const uint16_t*)Al,
        (const uint16_t*)Bh, (const uint16_t*)Bl,
        Cf, Cho, Clo, K, ldc, sC, azHi, azLo, bzHi, bzLo, alpha);
}

extern "C" void kernel_launch(void* const* d_in, const int* in_sizes, int n_in,
                              void* d_out, int out_size)
{
    (void)in_sizes; (void)n_in; (void)out_size;
    const float* x = (const float*)d_in[0];
    WPtrs4 wqk;
    wqk.p[0] = (const float*)d_in[1];   // Wq1
    wqk.p[1] = (const float*)d_in[2];   // Wk1
    wqk.p[2] = (const float*)d_in[3];   // Wq2
    wqk.p[3] = (const float*)d_in[4];   // Wk2
    WPtrs3 wv;
    wv.p[0] = (const float*)d_in[5];    // Wv
    wv.p[1] = (const float*)d_in[6];    // W1
    wv.p[2] = (const float*)d_in[7];    // W2
    float* out = (float*)d_out;

    fp16 *xh = sym_addr(g_xh),   *xl = sym_addr(g_xl);
    fp16 *Wvh = sym_addr(g_Wvh);
    fp16 *Wch = sym_addr(g_Wch), *Wcl = sym_addr(g_Wcl);
    fp16 *WTqh = sym_addr(g_WTqh), *WTql = sym_addr(g_WTql);
    fp16 *WTkh = sym_addr(g_WTkh), *WTkl = sym_addr(g_WTkl);
    fp16 *Nhh = sym_addr(g_Nh),  *Nll = sym_addr(g_Nl);
    fp16 *Thh = sym_addr(g_Th);
    fp16 *Vth = sym_addr(g_Vth);
    fp16 *Acat = sym_addr(g_Acat);
    fp16 *Cc = sym_addr(g_C);
    float *S = sym_addr(g_S);

    const float scale = 1.0f / sqrtf((float)SEQ);

    // [0] conversions: x (fp16 pair), Wv (fp16 hi), Wcat=[W1|-W2] (fp16 pair)
    convert_all<<<dim3(1024, 2), 256>>>(x, wv, xh, xl, Wvh, Wch, Wcl);

    // [1] transposes: Wq1,Wk1,Wq2,Wk2 -> WTq/WTk fp16 pairs
    transpose_pairs<<<dim3(SEQ / 32, SEQ / 32, 4), dim3(32, 8)>>>(
        wqk, WTqh, WTql, WTkh, WTkl);

    // [2] N_i = WTk_i @ WTq_i^T  (fp16 3-prod -> fp16 pair)   [6 pu]
    launch_g<3, 3>(WTkh, WTkl, 0, SEQ, WTqh, WTql, 0, SEQ,
                   SEQ, SEQ, SEQ, SEQ, 2,
                   nullptr, Nhh, Nll, SSZ, 1.0f);

    // [3] T_i = X @ N_i^T  (fp16 2-prod -> fp16 hi)            [32 pu]
    launch_g<4, 2>(xh, xh, 0, 0, Nhh, Nll, 0, SEQ,
                   MROWS, SEQ, SEQ, SEQ, 2,
                   nullptr, Thh, nullptr, NTOT, 1.0f);

    // [4] Vt[h] = Wv @ X[h]^T  (fp16 1-prod -> fp16 hi)        [8 pu]
    launch_g<4, 1>(Wvh, Wvh, 0, 0, xh, xh, 0, SEQ,
                   SEQ, SEQ, SEQ, SEQ, NH,
                   nullptr, Vth, nullptr, SSZ, 1.0f);

    // [5] logits: S = scale * T_i[h] @ X[h]^T  (fp16 1-prod)   [16 pu]
    launch_g<0, 1>(Thh, Thh, MROWS, SEQ, xh, xh, 0, SEQ,
                   SEQ, SEQ, SEQ, SEQ, 2 * NH,
                   S, nullptr, nullptr, SSZ, scale);

    // [6] softmax rows -> Acat fp16 hi-only (ld 4096)
    softmax_cat<<<2 * MROWS, 256>>>(S, Acat);

    // [7] circle[h]*4096 = (64 * Acat[h] @ Wcat^T)^2  (2-prod) [32 pu]
    launch_g<2, 2>(Acat, Acat, 0, SEQ, Wch, Wcl, 0, 0,
                   SEQ, SEQ, 2 * SEQ, SEQ, NH,
                   nullptr, Cc, nullptr, SSZ, 64.0f);

    // [8] out[h] = (1/4096) * circle4096[h] @ Vt[h]^T (1-prod) [8 pu]
    launch_g<0, 1>(Cc, Cc, 0, SEQ, Vth, Vth, 0, SEQ,
                   SEQ, SEQ, SEQ, SEQ, NH,
                   out, nullptr, nullptr, SSZ, 1.0f / 4096.0f);
}